// round 1
// baseline (speedup 1.0000x reference)
#include <cuda_runtime.h>
#include <math.h>

// Problem constants
#define B_ 4
#define N_ 2048
#define D_ 1024
#define H_ 16
#define HD_ 64
#define M_ (B_ * N_)          // 8192 rows
#define SCALE_ (1.0f / 64.0f)
#define NEG_ (-10000.0f)

// Scratch (static device globals — no runtime allocation allowed)
__device__ float g_q[M_ * D_];
__device__ float g_k[M_ * D_];
__device__ float g_v[M_ * D_];
__device__ float g_o[M_ * D_];

// ---------------------------------------------------------------------------
// SGEMM: C[m][n] = sum_k A[m][k] * W[n][k] (+ bias[n])
// A: [M x K] row-major, W: [N x K] row-major (i.e. computes A @ W^T)
// Block tile 128x128, BK=8, 256 threads, 8x8 per-thread microtile.
// ---------------------------------------------------------------------------
__global__ __launch_bounds__(256) void sgemm_nt(
    const float* __restrict__ A, const float* __restrict__ W,
    const float* __restrict__ bias, float* __restrict__ C,
    int M, int N, int K)
{
    __shared__ float As[8][128];
    __shared__ float Bs[8][128];

    const int tid  = threadIdx.x;
    const int bm   = blockIdx.y * 128;
    const int bn   = blockIdx.x * 128;
    const int lrow = tid >> 1;          // 0..127
    const int lcol = (tid & 1) << 2;    // 0 or 4
    const int trow = (tid >> 4) << 3;   // 0..120 step 8
    const int tcol = (tid & 15) << 3;

    const float* Aptr = A + (bm + lrow) * K + lcol;
    const float* Wptr = W + (bn + lrow) * K + lcol;

    float acc[8][8];
#pragma unroll
    for (int i = 0; i < 8; i++)
#pragma unroll
        for (int j = 0; j < 8; j++) acc[i][j] = 0.0f;

    for (int k0 = 0; k0 < K; k0 += 8) {
        float4 av = *(const float4*)(Aptr + k0);
        float4 wv = *(const float4*)(Wptr + k0);
        As[lcol + 0][lrow] = av.x;
        As[lcol + 1][lrow] = av.y;
        As[lcol + 2][lrow] = av.z;
        As[lcol + 3][lrow] = av.w;
        Bs[lcol + 0][lrow] = wv.x;
        Bs[lcol + 1][lrow] = wv.y;
        Bs[lcol + 2][lrow] = wv.z;
        Bs[lcol + 3][lrow] = wv.w;
        __syncthreads();

#pragma unroll
        for (int kk = 0; kk < 8; kk++) {
            float a[8], b[8];
            *(float4*)(a)     = *(const float4*)&As[kk][trow];
            *(float4*)(a + 4) = *(const float4*)&As[kk][trow + 4];
            *(float4*)(b)     = *(const float4*)&Bs[kk][tcol];
            *(float4*)(b + 4) = *(const float4*)&Bs[kk][tcol + 4];
#pragma unroll
            for (int i = 0; i < 8; i++)
#pragma unroll
                for (int j = 0; j < 8; j++)
                    acc[i][j] = fmaf(a[i], b[j], acc[i][j]);
        }
        __syncthreads();
    }

#pragma unroll
    for (int i = 0; i < 8; i++) {
#pragma unroll
        for (int j = 0; j < 8; j += 4) {
            float4 r;
            float b0 = bias ? bias[bn + tcol + j + 0] : 0.0f;
            float b1 = bias ? bias[bn + tcol + j + 1] : 0.0f;
            float b2 = bias ? bias[bn + tcol + j + 2] : 0.0f;
            float b3 = bias ? bias[bn + tcol + j + 3] : 0.0f;
            r.x = acc[i][j + 0] + b0;
            r.y = acc[i][j + 1] + b1;
            r.z = acc[i][j + 2] + b2;
            r.w = acc[i][j + 3] + b3;
            *(float4*)&C[(bm + trow + i) * N + bn + tcol + j] = r;
        }
    }
}

// ---------------------------------------------------------------------------
// RoPE (interleaved), in-place on a [B*N, D] buffer; per head of HD=64.
// Double trig so correctness survives --use_fast_math; angle rounded to f32
// exactly like the reference (f32 pos * f32 inv_freq).
// ---------------------------------------------------------------------------
__global__ void rope_kernel(float* __restrict__ t)
{
    int gid = blockIdx.x * blockDim.x + threadIdx.x;   // one thread per pair
    const int total = M_ * (D_ / 2);
    if (gid >= total) return;
    int row = gid >> 9;         // / (D/2 = 512)
    int p   = gid & 511;
    int h   = p >> 5;           // head
    int i   = p & 31;           // pair index within head (0..31)
    int pos = row & (N_ - 1);   // row % N

    // inv_freq = 10000^(-(2i)/64), rounded to f32 (match reference)
    float inv_f = (float)pow(10000.0, -(double)(2 * i) / 64.0);
    float ang   = (float)pos * inv_f;
    double c = cos((double)ang);
    double s = sin((double)ang);

    int base = row * D_ + h * HD_ + 2 * i;
    float x1 = t[base];
    float x2 = t[base + 1];
    t[base]     = (float)(x1 * c - x2 * s);
    t[base + 1] = (float)(x2 * c + x1 * s);
}

// ---------------------------------------------------------------------------
// Causal flash attention. One block = (b, h, 64-query tile).
// Smem (dynamic, stride 68 to dodge conflicts):
//   Qs = Q^T  [d][r]  (scaled by SCALE at load)
//   KV = K^T  [d][c]  then reused as V [j][c]
//   Ps = P^T  [j][r]
// 256 threads = 16x16, each owns a 4x4 microtile. Row softmax state (m,l)
// lives in registers, replicated across the 16 lanes of each row group via
// warp butterfly reductions.
// ---------------------------------------------------------------------------
#define FLASH_LDS 68
#define FLASH_SMEM (3 * 64 * FLASH_LDS * sizeof(float))

__global__ __launch_bounds__(256) void flash_kernel(
    const float* __restrict__ q, const float* __restrict__ k,
    const float* __restrict__ v, float* __restrict__ o)
{
    extern __shared__ float sm[];
    float* Qs = sm;
    float* KV = sm + 64 * FLASH_LDS;
    float* Ps = sm + 2 * 64 * FLASH_LDS;

    const int tid = threadIdx.x;
    const int qb = blockIdx.x, h = blockIdx.y, b = blockIdx.z;
    const int tx = tid & 15, ty = tid >> 4;
    const int r0 = ty * 4, c0 = tx * 4;

    const float* qbase = q + (b * N_ + qb * 64) * D_ + h * HD_;
    const float* kbase = k + b * N_ * D_ + h * HD_;
    const float* vbase = v + b * N_ * D_ + h * HD_;

    // Load Q^T, pre-scaled
    for (int i = tid; i < 4096; i += 256) {
        int r = i >> 6, d = i & 63;
        Qs[d * FLASH_LDS + r] = qbase[r * D_ + d] * SCALE_;
    }

    float m[4], l[4], Oacc[4][4];
#pragma unroll
    for (int i = 0; i < 4; i++) {
        m[i] = -1e30f;
        l[i] = 0.0f;
#pragma unroll
        for (int j = 0; j < 4; j++) Oacc[i][j] = 0.0f;
    }

    for (int kb = 0; kb <= qb; kb++) {
        __syncthreads();   // prior P@V (and Q store on first iter) complete
        // Load K^T
        for (int i = tid; i < 4096; i += 256) {
            int c = i >> 6, d = i & 63;
            KV[d * FLASH_LDS + c] = kbase[(kb * 64 + c) * D_ + d];
        }
        __syncthreads();

        // S = Q K^T  (already scaled)
        float S[4][4];
#pragma unroll
        for (int i = 0; i < 4; i++)
#pragma unroll
            for (int j = 0; j < 4; j++) S[i][j] = 0.0f;
        for (int d = 0; d < 64; d++) {
            float4 a  = *(const float4*)&Qs[d * FLASH_LDS + r0];
            float4 bb = *(const float4*)&KV[d * FLASH_LDS + c0];
            const float av[4] = {a.x, a.y, a.z, a.w};
            const float bv[4] = {bb.x, bb.y, bb.z, bb.w};
#pragma unroll
            for (int i = 0; i < 4; i++)
#pragma unroll
                for (int j = 0; j < 4; j++)
                    S[i][j] = fmaf(av[i], bv[j], S[i][j]);
        }

        if (kb == qb) {   // causal mask within diagonal tile
#pragma unroll
            for (int i = 0; i < 4; i++)
#pragma unroll
                for (int j = 0; j < 4; j++)
                    if (c0 + j > r0 + i) S[i][j] += NEG_;
        }

        // Online softmax
        float alpha[4];
#pragma unroll
        for (int i = 0; i < 4; i++) {
            float mx = fmaxf(fmaxf(S[i][0], S[i][1]), fmaxf(S[i][2], S[i][3]));
#pragma unroll
            for (int off = 1; off < 16; off <<= 1)
                mx = fmaxf(mx, __shfl_xor_sync(0xffffffffu, mx, off));
            float mn = fmaxf(m[i], mx);
            alpha[i] = expf(m[i] - mn);
            m[i] = mn;
            float rs = 0.0f;
#pragma unroll
            for (int j = 0; j < 4; j++) {
                S[i][j] = expf(S[i][j] - mn);
                rs += S[i][j];
            }
#pragma unroll
            for (int off = 1; off < 16; off <<= 1)
                rs += __shfl_xor_sync(0xffffffffu, rs, off);
            l[i] = l[i] * alpha[i] + rs;
#pragma unroll
            for (int j = 0; j < 4; j++) Oacc[i][j] *= alpha[i];
        }

        __syncthreads();   // all warps done reading K from KV
        // Store P^T; load V into KV
#pragma unroll
        for (int i = 0; i < 4; i++)
#pragma unroll
            for (int j = 0; j < 4; j++)
                Ps[(c0 + j) * FLASH_LDS + (r0 + i)] = S[i][j];
        for (int i = tid; i < 4096; i += 256) {
            int jr = i >> 6, c = i & 63;
            KV[jr * FLASH_LDS + c] = vbase[(kb * 64 + jr) * D_ + c];
        }
        __syncthreads();

        // O += P @ V
        for (int j = 0; j < 64; j++) {
            float4 p  = *(const float4*)&Ps[j * FLASH_LDS + r0];
            float4 vv = *(const float4*)&KV[j * FLASH_LDS + c0];
            const float pv[4] = {p.x, p.y, p.z, p.w};
            const float vvv[4] = {vv.x, vv.y, vv.z, vv.w};
#pragma unroll
            for (int i = 0; i < 4; i++)
#pragma unroll
                for (int jj = 0; jj < 4; jj++)
                    Oacc[i][jj] = fmaf(pv[i], vvv[jj], Oacc[i][jj]);
        }
    }

    // Normalize and write out
    float* obase = o + (b * N_ + qb * 64) * D_ + h * HD_;
#pragma unroll
    for (int i = 0; i < 4; i++) {
        float invl = 1.0f / l[i];
#pragma unroll
        for (int j = 0; j < 4; j++)
            obase[(r0 + i) * D_ + c0 + j] = Oacc[i][j] * invl;
    }
}

// ---------------------------------------------------------------------------
extern "C" void kernel_launch(void* const* d_in, const int* in_sizes, int n_in,
                              void* d_out, int out_size)
{
    const float* x  = (const float*)d_in[0];
    const float* Wq = (const float*)d_in[1];
    const float* Wk = (const float*)d_in[2];
    const float* Wv = (const float*)d_in[3];
    const float* Wo = (const float*)d_in[4];
    const float* bo = (const float*)d_in[5];
    float* out = (float*)d_out;

    float *q, *k, *v, *o;
    cudaGetSymbolAddress((void**)&q, g_q);
    cudaGetSymbolAddress((void**)&k, g_k);
    cudaGetSymbolAddress((void**)&v, g_v);
    cudaGetSymbolAddress((void**)&o, g_o);

    cudaFuncSetAttribute(flash_kernel,
                         cudaFuncAttributeMaxDynamicSharedMemorySize,
                         (int)FLASH_SMEM);

    dim3 gemm_grid(D_ / 128, M_ / 128);   // (8, 64)
    sgemm_nt<<<gemm_grid, 256>>>(x, Wq, nullptr, q, M_, D_, D_);
    sgemm_nt<<<gemm_grid, 256>>>(x, Wk, nullptr, k, M_, D_, D_);
    sgemm_nt<<<gemm_grid, 256>>>(x, Wv, nullptr, v, M_, D_, D_);

    int pairs = M_ * (D_ / 2);
    rope_kernel<<<(pairs + 255) / 256, 256>>>(q);
    rope_kernel<<<(pairs + 255) / 256, 256>>>(k);

    dim3 fgrid(N_ / 64, H_, B_);          // (32, 16, 4)
    flash_kernel<<<fgrid, 256, FLASH_SMEM>>>(q, k, v, o);

    sgemm_nt<<<gemm_grid, 256>>>(o, Wo, bo, out, M_, D_, D_);
}

// round 2
// speedup vs baseline: 1.6282x; 1.6282x over previous
#include <cuda_runtime.h>
#include <math.h>

// Problem constants
#define B_ 4
#define N_ 2048
#define D_ 1024
#define H_ 16
#define HD_ 64
#define M_ (B_ * N_)          // 8192 rows
#define SCALE_ (1.0f / 64.0f)
#define NEG_ (-10000.0f)

// Scratch (static device globals — no runtime allocation allowed)
__device__ float g_q[M_ * D_];
__device__ float g_k[M_ * D_];
__device__ float g_v[M_ * D_];
__device__ float g_o[M_ * D_];
__device__ float2 g_cs[N_ * 32];   // cos/sin table: (pos, pair) -> (cos, sin)

// ---------------------------------------------------------------------------
// SGEMM: C[m][n] = sum_k A[m][k] * W[n][k] (+ bias[n])
// A: [M x K] row-major, W: [N x K] row-major (i.e. computes A @ W^T)
// Block tile 128x128, BK=8, 256 threads, 8x8 per-thread microtile.
// ---------------------------------------------------------------------------
__global__ __launch_bounds__(256) void sgemm_nt(
    const float* __restrict__ A, const float* __restrict__ W,
    const float* __restrict__ bias, float* __restrict__ C,
    int M, int N, int K)
{
    __shared__ float As[8][128];
    __shared__ float Bs[8][128];

    const int tid  = threadIdx.x;
    const int bm   = blockIdx.y * 128;
    const int bn   = blockIdx.x * 128;
    const int lrow = tid >> 1;          // 0..127
    const int lcol = (tid & 1) << 2;    // 0 or 4
    const int trow = (tid >> 4) << 3;   // 0..120 step 8
    const int tcol = (tid & 15) << 3;

    const float* Aptr = A + (bm + lrow) * K + lcol;
    const float* Wptr = W + (bn + lrow) * K + lcol;

    float acc[8][8];
#pragma unroll
    for (int i = 0; i < 8; i++)
#pragma unroll
        for (int j = 0; j < 8; j++) acc[i][j] = 0.0f;

    for (int k0 = 0; k0 < K; k0 += 8) {
        float4 av = *(const float4*)(Aptr + k0);
        float4 wv = *(const float4*)(Wptr + k0);
        As[lcol + 0][lrow] = av.x;
        As[lcol + 1][lrow] = av.y;
        As[lcol + 2][lrow] = av.z;
        As[lcol + 3][lrow] = av.w;
        Bs[lcol + 0][lrow] = wv.x;
        Bs[lcol + 1][lrow] = wv.y;
        Bs[lcol + 2][lrow] = wv.z;
        Bs[lcol + 3][lrow] = wv.w;
        __syncthreads();

#pragma unroll
        for (int kk = 0; kk < 8; kk++) {
            float a[8], b[8];
            *(float4*)(a)     = *(const float4*)&As[kk][trow];
            *(float4*)(a + 4) = *(const float4*)&As[kk][trow + 4];
            *(float4*)(b)     = *(const float4*)&Bs[kk][tcol];
            *(float4*)(b + 4) = *(const float4*)&Bs[kk][tcol + 4];
#pragma unroll
            for (int i = 0; i < 8; i++)
#pragma unroll
                for (int j = 0; j < 8; j++)
                    acc[i][j] = fmaf(a[i], b[j], acc[i][j]);
        }
        __syncthreads();
    }

#pragma unroll
    for (int i = 0; i < 8; i++) {
#pragma unroll
        for (int j = 0; j < 8; j += 4) {
            float4 r;
            float b0 = bias ? bias[bn + tcol + j + 0] : 0.0f;
            float b1 = bias ? bias[bn + tcol + j + 1] : 0.0f;
            float b2 = bias ? bias[bn + tcol + j + 2] : 0.0f;
            float b3 = bias ? bias[bn + tcol + j + 3] : 0.0f;
            r.x = acc[i][j + 0] + b0;
            r.y = acc[i][j + 1] + b1;
            r.z = acc[i][j + 2] + b2;
            r.w = acc[i][j + 3] + b3;
            *(float4*)&C[(bm + trow + i) * N + bn + tcol + j] = r;
        }
    }
}

// ---------------------------------------------------------------------------
// RoPE cos/sin table build: one thread per (pos, pair). Only 65536 threads
// do the expensive double-precision trig (vs 4.2M before).
// ---------------------------------------------------------------------------
__global__ void build_cs_kernel()
{
    int gid = blockIdx.x * blockDim.x + threadIdx.x;
    if (gid >= N_ * 32) return;
    int pos = gid >> 5;
    int i   = gid & 31;
    // inv_freq = 10000^(-(2i)/64), rounded to f32 (match reference)
    float inv_f = (float)pow(10000.0, -(double)(2 * i) / 64.0);
    float ang   = (float)pos * inv_f;
    g_cs[gid] = make_float2((float)cos((double)ang), (float)sin((double)ang));
}

// ---------------------------------------------------------------------------
// RoPE apply (interleaved), fused over Q and K. One thread per pair,
// float2 vectorized load/store, f32 FMA math, table lookup for cos/sin.
// ---------------------------------------------------------------------------
__global__ void rope_apply_kernel(float* __restrict__ q, float* __restrict__ k)
{
    const int total = M_ * (D_ / 2);          // pairs per buffer
    int gid = blockIdx.x * blockDim.x + threadIdx.x;
    float* t = q;
    if (gid >= total) { t = k; gid -= total; }

    int row = gid >> 9;         // / (D/2 = 512)
    int p   = gid & 511;
    int i   = p & 31;           // pair index within head
    int pos = row & (N_ - 1);   // row % N

    float2 cs = g_cs[pos * 32 + i];
    float2* ptr = (float2*)(t + row * D_) + p;   // pair p = interleaved (x1,x2)
    float2 xv = *ptr;
    *ptr = make_float2(fmaf(xv.x, cs.x, -xv.y * cs.y),
                       fmaf(xv.y, cs.x,  xv.x * cs.y));
}

// ---------------------------------------------------------------------------
// Causal flash attention. One block = (b, h, 64-query tile).
// Smem (dynamic, stride 68 to dodge conflicts):
//   Qs = Q^T  [d][r]  (scaled by SCALE at load)
//   KV = K^T  [d][c]  then reused as V [j][c]
//   Ps = P^T  [j][r]
// 256 threads = 16x16, each owns a 4x4 microtile. Row softmax state (m,l)
// lives in registers, replicated across the 16 lanes of each row group via
// warp butterfly reductions.
// ---------------------------------------------------------------------------
#define FLASH_LDS 68
#define FLASH_SMEM (3 * 64 * FLASH_LDS * sizeof(float))

__global__ __launch_bounds__(256) void flash_kernel(
    const float* __restrict__ q, const float* __restrict__ k,
    const float* __restrict__ v, float* __restrict__ o)
{
    extern __shared__ float sm[];
    float* Qs = sm;
    float* KV = sm + 64 * FLASH_LDS;
    float* Ps = sm + 2 * 64 * FLASH_LDS;

    const int tid = threadIdx.x;
    const int qb = blockIdx.x, h = blockIdx.y, b = blockIdx.z;
    const int tx = tid & 15, ty = tid >> 4;
    const int r0 = ty * 4, c0 = tx * 4;

    const float* qbase = q + (b * N_ + qb * 64) * D_ + h * HD_;
    const float* kbase = k + b * N_ * D_ + h * HD_;
    const float* vbase = v + b * N_ * D_ + h * HD_;

    // Load Q^T, pre-scaled
    for (int i = tid; i < 4096; i += 256) {
        int r = i >> 6, d = i & 63;
        Qs[d * FLASH_LDS + r] = qbase[r * D_ + d] * SCALE_;
    }

    float m[4], l[4], Oacc[4][4];
#pragma unroll
    for (int i = 0; i < 4; i++) {
        m[i] = -1e30f;
        l[i] = 0.0f;
#pragma unroll
        for (int j = 0; j < 4; j++) Oacc[i][j] = 0.0f;
    }

    for (int kb = 0; kb <= qb; kb++) {
        __syncthreads();   // prior P@V (and Q store on first iter) complete
        // Load K^T
        for (int i = tid; i < 4096; i += 256) {
            int c = i >> 6, d = i & 63;
            KV[d * FLASH_LDS + c] = kbase[(kb * 64 + c) * D_ + d];
        }
        __syncthreads();

        // S = Q K^T  (already scaled)
        float S[4][4];
#pragma unroll
        for (int i = 0; i < 4; i++)
#pragma unroll
            for (int j = 0; j < 4; j++) S[i][j] = 0.0f;
        for (int d = 0; d < 64; d++) {
            float4 a  = *(const float4*)&Qs[d * FLASH_LDS + r0];
            float4 bb = *(const float4*)&KV[d * FLASH_LDS + c0];
            const float av[4] = {a.x, a.y, a.z, a.w};
            const float bv[4] = {bb.x, bb.y, bb.z, bb.w};
#pragma unroll
            for (int i = 0; i < 4; i++)
#pragma unroll
                for (int j = 0; j < 4; j++)
                    S[i][j] = fmaf(av[i], bv[j], S[i][j]);
        }

        if (kb == qb) {   // causal mask within diagonal tile
#pragma unroll
            for (int i = 0; i < 4; i++)
#pragma unroll
                for (int j = 0; j < 4; j++)
                    if (c0 + j > r0 + i) S[i][j] += NEG_;
        }

        // Online softmax
        float alpha[4];
#pragma unroll
        for (int i = 0; i < 4; i++) {
            float mx = fmaxf(fmaxf(S[i][0], S[i][1]), fmaxf(S[i][2], S[i][3]));
#pragma unroll
            for (int off = 1; off < 16; off <<= 1)
                mx = fmaxf(mx, __shfl_xor_sync(0xffffffffu, mx, off));
            float mn = fmaxf(m[i], mx);
            alpha[i] = expf(m[i] - mn);
            m[i] = mn;
            float rs = 0.0f;
#pragma unroll
            for (int j = 0; j < 4; j++) {
                S[i][j] = expf(S[i][j] - mn);
                rs += S[i][j];
            }
#pragma unroll
            for (int off = 1; off < 16; off <<= 1)
                rs += __shfl_xor_sync(0xffffffffu, rs, off);
            l[i] = l[i] * alpha[i] + rs;
#pragma unroll
            for (int j = 0; j < 4; j++) Oacc[i][j] *= alpha[i];
        }

        __syncthreads();   // all warps done reading K from KV
        // Store P^T; load V into KV
#pragma unroll
        for (int i = 0; i < 4; i++)
#pragma unroll
            for (int j = 0; j < 4; j++)
                Ps[(c0 + j) * FLASH_LDS + (r0 + i)] = S[i][j];
        for (int i = tid; i < 4096; i += 256) {
            int jr = i >> 6, c = i & 63;
            KV[jr * FLASH_LDS + c] = vbase[(kb * 64 + jr) * D_ + c];
        }
        __syncthreads();

        // O += P @ V
        for (int j = 0; j < 64; j++) {
            float4 p  = *(const float4*)&Ps[j * FLASH_LDS + r0];
            float4 vv = *(const float4*)&KV[j * FLASH_LDS + c0];
            const float pv[4] = {p.x, p.y, p.z, p.w};
            const float vvv[4] = {vv.x, vv.y, vv.z, vv.w};
#pragma unroll
            for (int i = 0; i < 4; i++)
#pragma unroll
                for (int jj = 0; jj < 4; jj++)
                    Oacc[i][jj] = fmaf(pv[i], vvv[jj], Oacc[i][jj]);
        }
    }

    // Normalize and write out
    float* obase = o + (b * N_ + qb * 64) * D_ + h * HD_;
#pragma unroll
    for (int i = 0; i < 4; i++) {
        float invl = 1.0f / l[i];
#pragma unroll
        for (int j = 0; j < 4; j++)
            obase[(r0 + i) * D_ + c0 + j] = Oacc[i][j] * invl;
    }
}

// ---------------------------------------------------------------------------
extern "C" void kernel_launch(void* const* d_in, const int* in_sizes, int n_in,
                              void* d_out, int out_size)
{
    const float* x  = (const float*)d_in[0];
    const float* Wq = (const float*)d_in[1];
    const float* Wk = (const float*)d_in[2];
    const float* Wv = (const float*)d_in[3];
    const float* Wo = (const float*)d_in[4];
    const float* bo = (const float*)d_in[5];
    float* out = (float*)d_out;

    float *q, *k, *v, *o;
    cudaGetSymbolAddress((void**)&q, g_q);
    cudaGetSymbolAddress((void**)&k, g_k);
    cudaGetSymbolAddress((void**)&v, g_v);
    cudaGetSymbolAddress((void**)&o, g_o);

    cudaFuncSetAttribute(flash_kernel,
                         cudaFuncAttributeMaxDynamicSharedMemorySize,
                         (int)FLASH_SMEM);

    // cos/sin table (cheap; overlaps nothing it shouldn't — writes g_cs only)
    build_cs_kernel<<<(N_ * 32 + 255) / 256, 256>>>();

    dim3 gemm_grid(D_ / 128, M_ / 128);   // (8, 64)
    sgemm_nt<<<gemm_grid, 256>>>(x, Wq, nullptr, q, M_, D_, D_);
    sgemm_nt<<<gemm_grid, 256>>>(x, Wk, nullptr, k, M_, D_, D_);
    sgemm_nt<<<gemm_grid, 256>>>(x, Wv, nullptr, v, M_, D_, D_);

    // fused RoPE on Q and K
    int pairs2 = 2 * M_ * (D_ / 2);
    rope_apply_kernel<<<(pairs2 + 255) / 256, 256>>>(q, k);

    dim3 fgrid(N_ / 64, H_, B_);          // (32, 16, 4)
    flash_kernel<<<fgrid, 256, FLASH_SMEM>>>(q, k, v, o);

    sgemm_nt<<<gemm_grid, 256>>>(o, Wo, bo, out, M_, D_, D_);
}

// round 5
// speedup vs baseline: 2.3706x; 1.4560x over previous
#include <cuda_runtime.h>
#include <cuda_bf16.h>
#include <math.h>
#include <cstdint>

// Problem constants
#define B_ 4
#define N_ 2048
#define D_ 1024
#define H_ 16
#define HD_ 64
#define M_ (B_ * N_)          // 8192 rows
#define K3_ (3 * D_)          // 3072: [hi|lo|hi] x [hi|hi|lo] split concat
#define SCALE_ (1.0f / 64.0f)
#define NEG_ (-10000.0f)

// Scratch (static device globals — no runtime allocation allowed)
__device__ float g_q[M_ * D_];
__device__ float g_k[M_ * D_];
__device__ float g_v[M_ * D_];
__device__ float g_o[M_ * D_];
__device__ float2 g_cs[N_ * 32];                 // RoPE cos/sin table
__device__ __nv_bfloat16 g_x2[(size_t)M_ * K3_]; // x  split [hi|lo|hi]
__device__ __nv_bfloat16 g_o2[(size_t)M_ * K3_]; // o  split [hi|lo|hi]
__device__ __nv_bfloat16 g_wq2[(size_t)D_ * K3_]; // W splits [hi|hi|lo]
__device__ __nv_bfloat16 g_wk2[(size_t)D_ * K3_];
__device__ __nv_bfloat16 g_wv2[(size_t)D_ * K3_];
__device__ __nv_bfloat16 g_wo2[(size_t)D_ * K3_];

__device__ __forceinline__ uint32_t smem_u32(const void* p) {
    uint32_t a;
    asm("{ .reg .u64 t; cvta.to.shared.u64 t, %1; cvt.u32.u64 %0, t; }"
        : "=r"(a) : "l"(p));
    return a;
}

// ===========================================================================
// hi/lo bf16 split with 3-way concat.
// wmode=0 (activations): row = [hi | lo | hi]
// wmode=1 (weights):     row = [hi | hi | lo]
// Dot(act_row, w_row) over 3072 = hi.hi + lo_a.hi_w + hi_a.lo_w  (exact to
// the dropped lo.lo ~ 2^-18 term).
// ===========================================================================
__global__ void split_kernel(const float* __restrict__ src,
                             __nv_bfloat16* __restrict__ dst, int rows, int wmode)
{
    int gid = blockIdx.x * blockDim.x + threadIdx.x;   // one float4
    int total = rows * (D_ / 4);
    if (gid >= total) return;
    int r = gid >> 8;            // / 256
    int c4 = gid & 255;          // float4 index within row
    float4 xv = ((const float4*)src)[gid];
    float xs[4] = {xv.x, xv.y, xv.z, xv.w};
    __nv_bfloat162 hi2[2], lo2[2];
#pragma unroll
    for (int j = 0; j < 2; j++) {
        __nv_bfloat16 h0 = __float2bfloat16(xs[2 * j]);
        __nv_bfloat16 h1 = __float2bfloat16(xs[2 * j + 1]);
        __nv_bfloat16 l0 = __float2bfloat16(xs[2 * j] - __bfloat162float(h0));
        __nv_bfloat16 l1 = __float2bfloat16(xs[2 * j + 1] - __bfloat162float(h1));
        hi2[j] = __nv_bfloat162{h0, h1};
        lo2[j] = __nv_bfloat162{l0, l1};
    }
    __nv_bfloat162* d0 = (__nv_bfloat162*)(dst + (size_t)r * K3_) + c4 * 2;
    __nv_bfloat162* d1 = (__nv_bfloat162*)(dst + (size_t)r * K3_ + D_) + c4 * 2;
    __nv_bfloat162* d2 = (__nv_bfloat162*)(dst + (size_t)r * K3_ + 2 * D_) + c4 * 2;
    d0[0] = hi2[0]; d0[1] = hi2[1];
    if (wmode) {      // weights: [hi | hi | lo]
        d1[0] = hi2[0]; d1[1] = hi2[1];
        d2[0] = lo2[0]; d2[1] = lo2[1];
    } else {          // activations: [hi | lo | hi]
        d1[0] = lo2[0]; d1[1] = lo2[1];
        d2[0] = hi2[0]; d2[1] = hi2[1];
    }
}

// ===========================================================================
// mma.sync bf16 GEMM: C[M x 1024] = A2[M x 3072] @ W2[1024 x 3072]^T (+bias)
// CTA 128x128, BK=32 bf16 chunks, cp.async double buffer.
// 8 warps = 2(m) x 4(n); warp tile 64 x 32 = 4 m16 x 4 n8 fragments.
// Both operands row-major [row, k] -> non-trans ldmatrix + mma.row.col.
// ===========================================================================
#define BK 32
#define PITCH 40                       // bf16 elems per smem row (80 B)
#define TILE_ELEMS (128 * PITCH)

__global__ __launch_bounds__(256) void mm_mma(
    const __nv_bfloat16* __restrict__ A, const __nv_bfloat16* __restrict__ Bw,
    const float* __restrict__ bias, float* __restrict__ C)
{
    __shared__ __nv_bfloat16 sA[2][TILE_ELEMS];
    __shared__ __nv_bfloat16 sB[2][TILE_ELEMS];

    const int tid  = threadIdx.x;
    const int lane = tid & 31;
    const int wid  = tid >> 5;
    const int wm   = wid >> 2;          // 0..1
    const int wn   = wid & 3;           // 0..3
    const int bm   = blockIdx.y * 128;
    const int bn   = blockIdx.x * 128;

    uint32_t sAb[2] = {smem_u32(sA[0]), smem_u32(sA[1])};
    uint32_t sBb[2] = {smem_u32(sB[0]), smem_u32(sB[1])};

    // ldmatrix lane addressing
    const uint32_t aRow = (uint32_t)(lane & 15);
    const uint32_t aKof = (uint32_t)((lane >> 4) << 3);
    const uint32_t bRow = (uint32_t)(lane & 7);
    const uint32_t bKof = (uint32_t)(((lane >> 3) & 1) << 3);

    float d[4][4][4];
#pragma unroll
    for (int mi = 0; mi < 4; mi++)
#pragma unroll
        for (int ni = 0; ni < 4; ni++)
#pragma unroll
            for (int r = 0; r < 4; r++) d[mi][ni][r] = 0.0f;

    const int NC = K3_ / BK;    // 96 chunks

    auto load_chunk = [&](int c, int buf) {
#pragma unroll
        for (int t = 0; t < 2; t++) {
            int l = tid + t * 256;
            int row = l >> 2, seg = l & 3;
            uint32_t dA = sAb[buf] + (uint32_t)(row * PITCH * 2 + seg * 16);
            uint32_t dB = sBb[buf] + (uint32_t)(row * PITCH * 2 + seg * 16);
            const __nv_bfloat16* gA = A  + (size_t)(bm + row) * K3_ + c * BK + seg * 8;
            const __nv_bfloat16* gB = Bw + (size_t)(bn + row) * K3_ + c * BK + seg * 8;
            asm volatile("cp.async.cg.shared.global [%0], [%1], 16;" :: "r"(dA), "l"(gA));
            asm volatile("cp.async.cg.shared.global [%0], [%1], 16;" :: "r"(dB), "l"(gB));
        }
        asm volatile("cp.async.commit_group;");
    };

    load_chunk(0, 0);

    for (int c = 0; c < NC; c++) {
        const int buf = c & 1;
        if (c + 1 < NC) {
            load_chunk(c + 1, buf ^ 1);
            asm volatile("cp.async.wait_group 1;");
        } else {
            asm volatile("cp.async.wait_group 0;");
        }
        __syncthreads();

#pragma unroll
        for (int ks = 0; ks < 2; ks++) {    // two k16 steps per chunk
            uint32_t a[4][4], b[4][2];
#pragma unroll
            for (int mi = 0; mi < 4; mi++) {
                uint32_t addr = sAb[buf] +
                    ((uint32_t)(wm * 64 + mi * 16) + aRow) * (PITCH * 2) +
                    ((uint32_t)(ks * 16) + aKof) * 2;
                asm volatile(
                    "ldmatrix.sync.aligned.m8n8.x4.shared.b16 {%0,%1,%2,%3}, [%4];"
                    : "=r"(a[mi][0]), "=r"(a[mi][1]), "=r"(a[mi][2]), "=r"(a[mi][3])
                    : "r"(addr));
            }
#pragma unroll
            for (int ni = 0; ni < 4; ni++) {
                uint32_t addr = sBb[buf] +
                    ((uint32_t)(wn * 32 + ni * 8) + bRow) * (PITCH * 2) +
                    ((uint32_t)(ks * 16) + bKof) * 2;
                asm volatile(
                    "ldmatrix.sync.aligned.m8n8.x2.shared.b16 {%0,%1}, [%2];"
                    : "=r"(b[ni][0]), "=r"(b[ni][1]) : "r"(addr));
            }
#pragma unroll
            for (int mi = 0; mi < 4; mi++)
#pragma unroll
                for (int ni = 0; ni < 4; ni++) {
                    asm volatile(
                        "mma.sync.aligned.m16n8k16.row.col.f32.bf16.bf16.f32 "
                        "{%0,%1,%2,%3}, {%4,%5,%6,%7}, {%8,%9}, {%0,%1,%2,%3};"
                        : "+f"(d[mi][ni][0]), "+f"(d[mi][ni][1]),
                          "+f"(d[mi][ni][2]), "+f"(d[mi][ni][3])
                        : "r"(a[mi][0]), "r"(a[mi][1]), "r"(a[mi][2]), "r"(a[mi][3]),
                          "r"(b[ni][0]), "r"(b[ni][1]));
                }
        }
        __syncthreads();
    }

    // Epilogue
#pragma unroll
    for (int mi = 0; mi < 4; mi++) {
        int r0 = bm + wm * 64 + mi * 16 + (lane >> 2);
#pragma unroll
        for (int ni = 0; ni < 4; ni++) {
            int cc = bn + wn * 32 + ni * 8 + ((lane & 3) << 1);
            float b0 = bias ? bias[cc] : 0.0f;
            float b1 = bias ? bias[cc + 1] : 0.0f;
            *(float2*)&C[(size_t)r0 * D_ + cc] =
                make_float2(d[mi][ni][0] + b0, d[mi][ni][1] + b1);
            *(float2*)&C[(size_t)(r0 + 8) * D_ + cc] =
                make_float2(d[mi][ni][2] + b0, d[mi][ni][3] + b1);
        }
    }
}

// ===========================================================================
// RoPE cos/sin table build (65536 threads do the DP trig once)
// ===========================================================================
__global__ void build_cs_kernel()
{
    int gid = blockIdx.x * blockDim.x + threadIdx.x;
    if (gid >= N_ * 32) return;
    int pos = gid >> 5;
    int i   = gid & 31;
    float inv_f = (float)pow(10000.0, -(double)(2 * i) / 64.0);
    float ang   = (float)pos * inv_f;
    g_cs[gid] = make_float2((float)cos((double)ang), (float)sin((double)ang));
}

// RoPE apply, fused over Q and K, table-driven, f32 math.
__global__ void rope_apply_kernel(float* __restrict__ q, float* __restrict__ k)
{
    const int total = M_ * (D_ / 2);
    int gid = blockIdx.x * blockDim.x + threadIdx.x;
    float* t = q;
    if (gid >= total) { t = k; gid -= total; }
    int row = gid >> 9;
    int p   = gid & 511;
    int i   = p & 31;
    int pos = row & (N_ - 1);
    float2 cs = g_cs[pos * 32 + i];
    float2* ptr = (float2*)(t + (size_t)row * D_) + p;
    float2 xv = *ptr;
    *ptr = make_float2(fmaf(xv.x, cs.x, -xv.y * cs.y),
                       fmaf(xv.y, cs.x,  xv.x * cs.y));
}

// ===========================================================================
// Causal flash attention (unchanged — round 6 target)
// ===========================================================================
#define FLASH_LDS 68
#define FLASH_SMEM (3 * 64 * FLASH_LDS * sizeof(float))

__global__ __launch_bounds__(256) void flash_kernel(
    const float* __restrict__ q, const float* __restrict__ k,
    const float* __restrict__ v, float* __restrict__ o)
{
    extern __shared__ float sm[];
    float* Qs = sm;
    float* KV = sm + 64 * FLASH_LDS;
    float* Ps = sm + 2 * 64 * FLASH_LDS;

    const int tid = threadIdx.x;
    const int qb = blockIdx.x, h = blockIdx.y, b = blockIdx.z;
    const int tx = tid & 15, ty = tid >> 4;
    const int r0 = ty * 4, c0 = tx * 4;

    const float* qbase = q + (size_t)(b * N_ + qb * 64) * D_ + h * HD_;
    const float* kbase = k + (size_t)b * N_ * D_ + h * HD_;
    const float* vbase = v + (size_t)b * N_ * D_ + h * HD_;

    for (int i = tid; i < 4096; i += 256) {
        int r = i >> 6, d = i & 63;
        Qs[d * FLASH_LDS + r] = qbase[r * D_ + d] * SCALE_;
    }

    float m[4], l[4], Oacc[4][4];
#pragma unroll
    for (int i = 0; i < 4; i++) {
        m[i] = -1e30f;
        l[i] = 0.0f;
#pragma unroll
        for (int j = 0; j < 4; j++) Oacc[i][j] = 0.0f;
    }

    for (int kb = 0; kb <= qb; kb++) {
        __syncthreads();
        for (int i = tid; i < 4096; i += 256) {
            int c = i >> 6, d = i & 63;
            KV[d * FLASH_LDS + c] = kbase[(size_t)(kb * 64 + c) * D_ + d];
        }
        __syncthreads();

        float S[4][4];
#pragma unroll
        for (int i = 0; i < 4; i++)
#pragma unroll
            for (int j = 0; j < 4; j++) S[i][j] = 0.0f;
        for (int d = 0; d < 64; d++) {
            float4 a  = *(const float4*)&Qs[d * FLASH_LDS + r0];
            float4 bb = *(const float4*)&KV[d * FLASH_LDS + c0];
            const float av[4] = {a.x, a.y, a.z, a.w};
            const float bv[4] = {bb.x, bb.y, bb.z, bb.w};
#pragma unroll
            for (int i = 0; i < 4; i++)
#pragma unroll
                for (int j = 0; j < 4; j++)
                    S[i][j] = fmaf(av[i], bv[j], S[i][j]);
        }

        if (kb == qb) {
#pragma unroll
            for (int i = 0; i < 4; i++)
#pragma unroll
                for (int j = 0; j < 4; j++)
                    if (c0 + j > r0 + i) S[i][j] += NEG_;
        }

        float alpha[4];
#pragma unroll
        for (int i = 0; i < 4; i++) {
            float mx = fmaxf(fmaxf(S[i][0], S[i][1]), fmaxf(S[i][2], S[i][3]));
#pragma unroll
            for (int off = 1; off < 16; off <<= 1)
                mx = fmaxf(mx, __shfl_xor_sync(0xffffffffu, mx, off));
            float mn = fmaxf(m[i], mx);
            alpha[i] = expf(m[i] - mn);
            m[i] = mn;
            float rs = 0.0f;
#pragma unroll
            for (int j = 0; j < 4; j++) {
                S[i][j] = expf(S[i][j] - mn);
                rs += S[i][j];
            }
#pragma unroll
            for (int off = 1; off < 16; off <<= 1)
                rs += __shfl_xor_sync(0xffffffffu, rs, off);
            l[i] = l[i] * alpha[i] + rs;
#pragma unroll
            for (int j = 0; j < 4; j++) Oacc[i][j] *= alpha[i];
        }

        __syncthreads();
#pragma unroll
        for (int i = 0; i < 4; i++)
#pragma unroll
            for (int j = 0; j < 4; j++)
                Ps[(c0 + j) * FLASH_LDS + (r0 + i)] = S[i][j];
        for (int i = tid; i < 4096; i += 256) {
            int jr = i >> 6, c = i & 63;
            KV[jr * FLASH_LDS + c] = vbase[(size_t)(kb * 64 + jr) * D_ + c];
        }
        __syncthreads();

        for (int j = 0; j < 64; j++) {
            float4 p  = *(const float4*)&Ps[j * FLASH_LDS + r0];
            float4 vv = *(const float4*)&KV[j * FLASH_LDS + c0];
            const float pv[4] = {p.x, p.y, p.z, p.w};
            const float vvv[4] = {vv.x, vv.y, vv.z, vv.w};
#pragma unroll
            for (int i = 0; i < 4; i++)
#pragma unroll
                for (int jj = 0; jj < 4; jj++)
                    Oacc[i][jj] = fmaf(pv[i], vvv[jj], Oacc[i][jj]);
        }
    }

    float* obase = o + (size_t)(b * N_ + qb * 64) * D_ + h * HD_;
#pragma unroll
    for (int i = 0; i < 4; i++) {
        float invl = 1.0f / l[i];
#pragma unroll
        for (int j = 0; j < 4; j++)
            obase[(r0 + i) * D_ + c0 + j] = Oacc[i][j] * invl;
    }
}

// ---------------------------------------------------------------------------
extern "C" void kernel_launch(void* const* d_in, const int* in_sizes, int n_in,
                              void* d_out, int out_size)
{
    const float* x  = (const float*)d_in[0];
    const float* Wq = (const float*)d_in[1];
    const float* Wk = (const float*)d_in[2];
    const float* Wv = (const float*)d_in[3];
    const float* Wo = (const float*)d_in[4];
    const float* bo = (const float*)d_in[5];
    float* out = (float*)d_out;

    float *q, *k, *v, *o;
    __nv_bfloat16 *x2, *o2, *wq2, *wk2, *wv2, *wo2;
    cudaGetSymbolAddress((void**)&q, g_q);
    cudaGetSymbolAddress((void**)&k, g_k);
    cudaGetSymbolAddress((void**)&v, g_v);
    cudaGetSymbolAddress((void**)&o, g_o);
    cudaGetSymbolAddress((void**)&x2, g_x2);
    cudaGetSymbolAddress((void**)&o2, g_o2);
    cudaGetSymbolAddress((void**)&wq2, g_wq2);
    cudaGetSymbolAddress((void**)&wk2, g_wk2);
    cudaGetSymbolAddress((void**)&wv2, g_wv2);
    cudaGetSymbolAddress((void**)&wo2, g_wo2);

    cudaFuncSetAttribute(flash_kernel, cudaFuncAttributeMaxDynamicSharedMemorySize,
                         (int)FLASH_SMEM);

    build_cs_kernel<<<(N_ * 32 + 255) / 256, 256>>>();

    // hi/lo splits: activations [hi|lo|hi], weights [hi|hi|lo]
    int xthreads = M_ * (D_ / 4);
    int wthreads = D_ * (D_ / 4);
    split_kernel<<<(xthreads + 255) / 256, 256>>>(x, x2, M_, 0);
    split_kernel<<<(wthreads + 255) / 256, 256>>>(Wq, wq2, D_, 1);
    split_kernel<<<(wthreads + 255) / 256, 256>>>(Wk, wk2, D_, 1);
    split_kernel<<<(wthreads + 255) / 256, 256>>>(Wv, wv2, D_, 1);
    split_kernel<<<(wthreads + 255) / 256, 256>>>(Wo, wo2, D_, 1);

    dim3 ggrid(D_ / 128, M_ / 128);   // (8, 64)
    mm_mma<<<ggrid, 256>>>(x2, wq2, nullptr, q);
    mm_mma<<<ggrid, 256>>>(x2, wk2, nullptr, k);
    mm_mma<<<ggrid, 256>>>(x2, wv2, nullptr, v);

    int pairs2 = 2 * M_ * (D_ / 2);
    rope_apply_kernel<<<(pairs2 + 255) / 256, 256>>>(q, k);

    dim3 fgrid(N_ / 64, H_, B_);      // (32, 16, 4)
    flash_kernel<<<fgrid, 256, FLASH_SMEM>>>(q, k, v, o);

    split_kernel<<<(xthreads + 255) / 256, 256>>>(o, o2, M_, 0);
    mm_mma<<<ggrid, 256>>>(o2, wo2, bo, out);
}

// round 6
// speedup vs baseline: 3.8566x; 1.6268x over previous
#include <cuda_runtime.h>
#include <cuda_bf16.h>
#include <math.h>
#include <cstdint>

// Problem constants
#define B_ 4
#define N_ 2048
#define D_ 1024
#define H_ 16
#define HD_ 64
#define M_ (B_ * N_)          // 8192 rows
#define K3_ (3 * D_)          // 3072: [hi|lo|hi] x [hi|hi|lo] split concat
#define SCALE_ (1.0f / 64.0f)
#define NEG_ (-10000.0f)

// Scratch (static device globals — no runtime allocation allowed)
__device__ float g_q[M_ * D_];
__device__ float g_k[M_ * D_];
__device__ float g_v[M_ * D_];
__device__ float g_o[M_ * D_];
__device__ float2 g_cs[N_ * 32];                 // RoPE cos/sin table
__device__ __nv_bfloat16 g_x2[(size_t)M_ * K3_]; // x  split [hi|lo|hi]
__device__ __nv_bfloat16 g_o2[(size_t)M_ * K3_]; // o  split [hi|lo|hi]
__device__ __nv_bfloat16 g_wq2[(size_t)D_ * K3_]; // W splits [hi|hi|lo]
__device__ __nv_bfloat16 g_wk2[(size_t)D_ * K3_];
__device__ __nv_bfloat16 g_wv2[(size_t)D_ * K3_];
__device__ __nv_bfloat16 g_wo2[(size_t)D_ * K3_];
// flash operands: hi/lo bf16, Q pre-scaled; V transposed per (b,h)
__device__ __nv_bfloat16 g_qh[(size_t)M_ * D_];
__device__ __nv_bfloat16 g_ql[(size_t)M_ * D_];
__device__ __nv_bfloat16 g_kh[(size_t)M_ * D_];
__device__ __nv_bfloat16 g_kl[(size_t)M_ * D_];
__device__ __nv_bfloat16 g_vth[(size_t)B_ * H_ * HD_ * N_];
__device__ __nv_bfloat16 g_vtl[(size_t)B_ * H_ * HD_ * N_];

__device__ __forceinline__ uint32_t smem_u32(const void* p) {
    uint32_t a;
    asm("{ .reg .u64 t; cvta.to.shared.u64 t, %1; cvt.u32.u64 %0, t; }"
        : "=r"(a) : "l"(p));
    return a;
}

#define CP16(dst, src) \
    asm volatile("cp.async.cg.shared.global [%0], [%1], 16;" :: "r"(dst), "l"(src))
#define LDMX4(r0, r1, r2, r3, addr) \
    asm volatile("ldmatrix.sync.aligned.m8n8.x4.shared.b16 {%0,%1,%2,%3}, [%4];" \
                 : "=r"(r0), "=r"(r1), "=r"(r2), "=r"(r3) : "r"(addr))
#define MMA4(dd, aa, b0, b1) \
    asm volatile("mma.sync.aligned.m16n8k16.row.col.f32.bf16.bf16.f32 " \
                 "{%0,%1,%2,%3}, {%4,%5,%6,%7}, {%8,%9}, {%0,%1,%2,%3};" \
                 : "+f"((dd)[0]), "+f"((dd)[1]), "+f"((dd)[2]), "+f"((dd)[3]) \
                 : "r"((aa)[0]), "r"((aa)[1]), "r"((aa)[2]), "r"((aa)[3]), \
                   "r"(b0), "r"(b1))

__device__ __forceinline__ void split_pack(float x, float y, uint32_t& hi, uint32_t& lo) {
    __nv_bfloat16 hx = __float2bfloat16(x), hy = __float2bfloat16(y);
    __nv_bfloat16 lx = __float2bfloat16(x - __bfloat162float(hx));
    __nv_bfloat16 ly = __float2bfloat16(y - __bfloat162float(hy));
    __nv_bfloat162 Hh{hx, hy}, Ll{lx, ly};
    hi = *(uint32_t*)&Hh;
    lo = *(uint32_t*)&Ll;
}

// ===========================================================================
// hi/lo bf16 split with 3-way concat (for projection GEMMs).
// wmode=0 (activations): [hi | lo | hi];  wmode=1 (weights): [hi | hi | lo]
// ===========================================================================
__global__ void split_kernel(const float* __restrict__ src,
                             __nv_bfloat16* __restrict__ dst, int rows, int wmode)
{
    int gid = blockIdx.x * blockDim.x + threadIdx.x;
    int total = rows * (D_ / 4);
    if (gid >= total) return;
    int r = gid >> 8;
    int c4 = gid & 255;
    float4 xv = ((const float4*)src)[gid];
    float xs[4] = {xv.x, xv.y, xv.z, xv.w};
    __nv_bfloat162 hi2[2], lo2[2];
#pragma unroll
    for (int j = 0; j < 2; j++) {
        __nv_bfloat16 h0 = __float2bfloat16(xs[2 * j]);
        __nv_bfloat16 h1 = __float2bfloat16(xs[2 * j + 1]);
        __nv_bfloat16 l0 = __float2bfloat16(xs[2 * j] - __bfloat162float(h0));
        __nv_bfloat16 l1 = __float2bfloat16(xs[2 * j + 1] - __bfloat162float(h1));
        hi2[j] = __nv_bfloat162{h0, h1};
        lo2[j] = __nv_bfloat162{l0, l1};
    }
    __nv_bfloat162* d0 = (__nv_bfloat162*)(dst + (size_t)r * K3_) + c4 * 2;
    __nv_bfloat162* d1 = (__nv_bfloat162*)(dst + (size_t)r * K3_ + D_) + c4 * 2;
    __nv_bfloat162* d2 = (__nv_bfloat162*)(dst + (size_t)r * K3_ + 2 * D_) + c4 * 2;
    d0[0] = hi2[0]; d0[1] = hi2[1];
    if (wmode) { d1[0] = hi2[0]; d1[1] = hi2[1]; d2[0] = lo2[0]; d2[1] = lo2[1]; }
    else       { d1[0] = lo2[0]; d1[1] = lo2[1]; d2[0] = hi2[0]; d2[1] = hi2[1]; }
}

// ===========================================================================
// mma.sync bf16 GEMM (projections): C = A2[Mx3072] @ W2[1024x3072]^T (+bias)
// ===========================================================================
#define BK 32
#define PITCH 40
#define TILE_ELEMS (128 * PITCH)

__global__ __launch_bounds__(256) void mm_mma(
    const __nv_bfloat16* __restrict__ A, const __nv_bfloat16* __restrict__ Bw,
    const float* __restrict__ bias, float* __restrict__ C)
{
    __shared__ __nv_bfloat16 sA[2][TILE_ELEMS];
    __shared__ __nv_bfloat16 sB[2][TILE_ELEMS];

    const int tid  = threadIdx.x;
    const int lane = tid & 31;
    const int wid  = tid >> 5;
    const int wm   = wid >> 2;
    const int wn   = wid & 3;
    const int bm   = blockIdx.y * 128;
    const int bn   = blockIdx.x * 128;

    uint32_t sAb[2] = {smem_u32(sA[0]), smem_u32(sA[1])};
    uint32_t sBb[2] = {smem_u32(sB[0]), smem_u32(sB[1])};

    const uint32_t aRow = (uint32_t)(lane & 15);
    const uint32_t aKof = (uint32_t)((lane >> 4) << 3);
    const uint32_t bRow = (uint32_t)(lane & 7);
    const uint32_t bKof = (uint32_t)(((lane >> 3) & 1) << 3);

    float d[4][4][4];
#pragma unroll
    for (int mi = 0; mi < 4; mi++)
#pragma unroll
        for (int ni = 0; ni < 4; ni++)
#pragma unroll
            for (int r = 0; r < 4; r++) d[mi][ni][r] = 0.0f;

    const int NC = K3_ / BK;

    auto load_chunk = [&](int c, int buf) {
#pragma unroll
        for (int t = 0; t < 2; t++) {
            int l = tid + t * 256;
            int row = l >> 2, seg = l & 3;
            uint32_t dA = sAb[buf] + (uint32_t)(row * PITCH * 2 + seg * 16);
            uint32_t dB = sBb[buf] + (uint32_t)(row * PITCH * 2 + seg * 16);
            const __nv_bfloat16* gA = A  + (size_t)(bm + row) * K3_ + c * BK + seg * 8;
            const __nv_bfloat16* gB = Bw + (size_t)(bn + row) * K3_ + c * BK + seg * 8;
            CP16(dA, gA);
            CP16(dB, gB);
        }
        asm volatile("cp.async.commit_group;");
    };

    load_chunk(0, 0);

    for (int c = 0; c < NC; c++) {
        const int buf = c & 1;
        if (c + 1 < NC) {
            load_chunk(c + 1, buf ^ 1);
            asm volatile("cp.async.wait_group 1;");
        } else {
            asm volatile("cp.async.wait_group 0;");
        }
        __syncthreads();

#pragma unroll
        for (int ks = 0; ks < 2; ks++) {
            uint32_t a[4][4], b[4][2];
#pragma unroll
            for (int mi = 0; mi < 4; mi++) {
                uint32_t addr = sAb[buf] +
                    ((uint32_t)(wm * 64 + mi * 16) + aRow) * (PITCH * 2) +
                    ((uint32_t)(ks * 16) + aKof) * 2;
                LDMX4(a[mi][0], a[mi][1], a[mi][2], a[mi][3], addr);
            }
#pragma unroll
            for (int ni = 0; ni < 4; ni++) {
                uint32_t addr = sBb[buf] +
                    ((uint32_t)(wn * 32 + ni * 8) + bRow) * (PITCH * 2) +
                    ((uint32_t)(ks * 16) + bKof) * 2;
                asm volatile(
                    "ldmatrix.sync.aligned.m8n8.x2.shared.b16 {%0,%1}, [%2];"
                    : "=r"(b[ni][0]), "=r"(b[ni][1]) : "r"(addr));
            }
#pragma unroll
            for (int mi = 0; mi < 4; mi++)
#pragma unroll
                for (int ni = 0; ni < 4; ni++)
                    MMA4(d[mi][ni], a[mi], b[ni][0], b[ni][1]);
        }
        __syncthreads();
    }

#pragma unroll
    for (int mi = 0; mi < 4; mi++) {
        int r0 = bm + wm * 64 + mi * 16 + (lane >> 2);
#pragma unroll
        for (int ni = 0; ni < 4; ni++) {
            int cc = bn + wn * 32 + ni * 8 + ((lane & 3) << 1);
            float b0 = bias ? bias[cc] : 0.0f;
            float b1 = bias ? bias[cc + 1] : 0.0f;
            *(float2*)&C[(size_t)r0 * D_ + cc] =
                make_float2(d[mi][ni][0] + b0, d[mi][ni][1] + b1);
            *(float2*)&C[(size_t)(r0 + 8) * D_ + cc] =
                make_float2(d[mi][ni][2] + b0, d[mi][ni][3] + b1);
        }
    }
}

// ===========================================================================
// RoPE cos/sin table build
// ===========================================================================
__global__ void build_cs_kernel()
{
    int gid = blockIdx.x * blockDim.x + threadIdx.x;
    if (gid >= N_ * 32) return;
    int pos = gid >> 5;
    int i   = gid & 31;
    float inv_f = (float)pow(10000.0, -(double)(2 * i) / 64.0);
    float ang   = (float)pos * inv_f;
    g_cs[gid] = make_float2((float)cos((double)ang), (float)sin((double)ang));
}

// ===========================================================================
// Fused RoPE + hi/lo split for Q (pre-scaled by SCALE_) and K.
// One thread per pair; writes bf16x2 hi/lo buffers.
// ===========================================================================
__global__ void rope_split_kernel(
    const float* __restrict__ q, const float* __restrict__ k,
    __nv_bfloat16* __restrict__ qh, __nv_bfloat16* __restrict__ ql,
    __nv_bfloat16* __restrict__ kh, __nv_bfloat16* __restrict__ kl)
{
    int gid = blockIdx.x * blockDim.x + threadIdx.x;
    if (gid >= M_ * 512) return;
    int row = gid >> 9;
    int p   = gid & 511;
    int i   = p & 31;
    int pos = row & (N_ - 1);
    float2 cs = g_cs[pos * 32 + i];

    float2 xq = ((const float2*)(q + (size_t)row * D_))[p];
    float qa = fmaf(xq.x, cs.x, -xq.y * cs.y) * SCALE_;
    float qb = fmaf(xq.y, cs.x,  xq.x * cs.y) * SCALE_;
    uint32_t qhi, qlo;
    split_pack(qa, qb, qhi, qlo);
    ((uint32_t*)(qh + (size_t)row * D_))[p] = qhi;
    ((uint32_t*)(ql + (size_t)row * D_))[p] = qlo;

    float2 xk = ((const float2*)(k + (size_t)row * D_))[p];
    float ka = fmaf(xk.x, cs.x, -xk.y * cs.y);
    float kb = fmaf(xk.y, cs.x,  xk.x * cs.y);
    uint32_t khi, klo;
    split_pack(ka, kb, khi, klo);
    ((uint32_t*)(kh + (size_t)row * D_))[p] = khi;
    ((uint32_t*)(kl + (size_t)row * D_))[p] = klo;
}

// ===========================================================================
// V split + transpose: v [b,n,h*64+d] f32 -> vth/vtl [b,h,d,n] bf16
// 64x64 tiles via smem.
// ===========================================================================
__global__ void v_split_t_kernel(const float* __restrict__ v,
                                 __nv_bfloat16* __restrict__ vth,
                                 __nv_bfloat16* __restrict__ vtl)
{
    __shared__ float tile[64][65];
    int n0 = blockIdx.x * 64, hh = blockIdx.y, b = blockIdx.z;
    int tid = threadIdx.x;
#pragma unroll
    for (int i = 0; i < 16; i++) {
        int idx = tid + i * 256;
        int r = idx >> 6, c = idx & 63;
        tile[r][c] = v[((size_t)(b * N_ + n0 + r)) * D_ + hh * HD_ + c];
    }
    __syncthreads();
#pragma unroll
    for (int i = 0; i < 16; i++) {
        int idx = tid + i * 256;
        int dd = idx >> 6, c = idx & 63;
        float val = tile[c][dd];
        __nv_bfloat16 hv = __float2bfloat16(val);
        __nv_bfloat16 lv = __float2bfloat16(val - __bfloat162float(hv));
        size_t off = ((size_t)((b * H_ + hh) * HD_ + dd)) * N_ + n0 + c;
        vth[off] = hv;
        vtl[off] = lv;
    }
}

// ===========================================================================
// Tensor-core causal flash attention with hi/lo split.
// CTA: 128 q-rows x one (b,h). 8 warps x 16 q-rows. K/V tiles 64 keys.
// S = Qh.Kh + Ql.Kh + Qh.Kl ; O += Ph.Vh + Pl.Vh + Ph.Vl (P from C-frag repack)
// ===========================================================================
#define FP 72                               // smem pitch (bf16 elems), 144 B
#define FL_SMEM ((256 * FP + 2 * 2 * 64 * FP + 2 * 2 * 64 * FP) * 2)

__global__ __launch_bounds__(256, 1) void flash_mma(
    const __nv_bfloat16* __restrict__ qh, const __nv_bfloat16* __restrict__ ql,
    const __nv_bfloat16* __restrict__ kh, const __nv_bfloat16* __restrict__ kl,
    const __nv_bfloat16* __restrict__ vth, const __nv_bfloat16* __restrict__ vtl,
    float* __restrict__ o)
{
    extern __shared__ __nv_bfloat16 sm[];
    __nv_bfloat16* sQh = sm;                      // [128][FP]
    __nv_bfloat16* sQl = sm + 128 * FP;
    __nv_bfloat16* sK  = sm + 256 * FP;           // [2 buf][2 hl][64][FP]
    __nv_bfloat16* sV  = sm + 256 * FP + 4 * 64 * FP;

    const int tid = threadIdx.x, lane = tid & 31, wid = tid >> 5;
    const int qb = blockIdx.x, h = blockIdx.y, b = blockIdx.z;
    const int qrow0 = qb * 128;

    // ---- Q load (hi+lo), group 0
    {
#pragma unroll
        for (int i = 0; i < 8; i++) {
            int t = tid + i * 256;              // 0..2047
            int tensor = t >> 10;               // 0=hi,1=lo
            int rem = t & 1023;
            int r = rem >> 3, s = rem & 7;
            uint32_t dst = smem_u32((tensor ? sQl : sQh) + r * FP) + s * 16;
            const __nv_bfloat16* src = (tensor ? ql : qh) +
                ((size_t)(b * N_ + qrow0 + r)) * D_ + h * HD_ + s * 8;
            CP16(dst, src);
        }
        asm volatile("cp.async.commit_group;");
    }

    auto load_kv = [&](int kb, int buf) {
#pragma unroll
        for (int i = 0; i < 8; i++) {
            int t = tid + i * 256;              // 0..2047
            int tensor = t >> 9;                // 0 Kh,1 Kl,2 Vh,3 Vl
            int rem = t & 511;
            int r = rem >> 3, s = rem & 7;
            uint32_t dst;
            const __nv_bfloat16* src;
            if (tensor < 2) {
                dst = smem_u32(sK + ((buf * 2 + tensor) * 64 + r) * FP) + s * 16;
                src = (tensor ? kl : kh) +
                    ((size_t)(b * N_ + kb * 64 + r)) * D_ + h * HD_ + s * 8;
            } else {
                dst = smem_u32(sV + ((buf * 2 + (tensor - 2)) * 64 + r) * FP) + s * 16;
                src = ((tensor == 3) ? vtl : vth) +
                    ((size_t)((b * H_ + h) * HD_ + r)) * N_ + kb * 64 + s * 8;
            }
            CP16(dst, src);
        }
        asm volatile("cp.async.commit_group;");
    };

    load_kv(0, 0);
    asm volatile("cp.async.wait_group 0;");
    __syncthreads();

    // ---- Q fragments (static across the loop)
    uint32_t fqh[4][4], fql[4][4];
    {
        uint32_t rowa = (uint32_t)(wid * 16 + (lane & 15));
        uint32_t cola = (uint32_t)(((lane >> 4) & 1) * 8);
        uint32_t bqh = smem_u32(sQh), bql = smem_u32(sQl);
#pragma unroll
        for (int ks = 0; ks < 4; ks++) {
            uint32_t off = (rowa * FP + ks * 16 + cola) * 2;
            LDMX4(fqh[ks][0], fqh[ks][1], fqh[ks][2], fqh[ks][3], bqh + off);
            LDMX4(fql[ks][0], fql[ks][1], fql[ks][2], fql[ks][3], bql + off);
        }
    }

    float m0 = -1e30f, m1 = -1e30f, l0 = 0.0f, l1 = 0.0f;
    float oacc[8][4];
#pragma unroll
    for (int f = 0; f < 8; f++)
#pragma unroll
        for (int r = 0; r < 4; r++) oacc[f][r] = 0.0f;

    const uint32_t rowb = (uint32_t)((lane & 7) + ((lane >> 4) & 1) * 8);
    const uint32_t colb8 = (uint32_t)(((lane >> 3) & 1) * 8);
    const int kbmax = 2 * qb + 1;

    for (int kb = 0; kb <= kbmax; kb++) {
        const int buf = kb & 1;
        if (kb) {
            asm volatile("cp.async.wait_group 0;");
            __syncthreads();
        }
        if (kb < kbmax) load_kv(kb + 1, buf ^ 1);   // overlap with compute

        // ---- S = Q.K^T with 3-way split
        float sacc[8][4];
#pragma unroll
        for (int f = 0; f < 8; f++)
#pragma unroll
            for (int r = 0; r < 4; r++) sacc[f][r] = 0.0f;

        uint32_t kbh = smem_u32(sK + (buf * 2 + 0) * 64 * FP);
        uint32_t kbl = smem_u32(sK + (buf * 2 + 1) * 64 * FP);
#pragma unroll
        for (int ks = 0; ks < 4; ks++) {
#pragma unroll
            for (int g = 0; g < 4; g++) {
                uint32_t b0, b1, b2, b3;
                uint32_t off = ((16 * g + rowb) * FP + ks * 16 + colb8) * 2;
                LDMX4(b0, b1, b2, b3, kbh + off);
                MMA4(sacc[2 * g],     fqh[ks], b0, b1);
                MMA4(sacc[2 * g + 1], fqh[ks], b2, b3);
                MMA4(sacc[2 * g],     fql[ks], b0, b1);
                MMA4(sacc[2 * g + 1], fql[ks], b2, b3);
            }
        }
#pragma unroll
        for (int ks = 0; ks < 4; ks++) {
#pragma unroll
            for (int g = 0; g < 4; g++) {
                uint32_t b0, b1, b2, b3;
                uint32_t off = ((16 * g + rowb) * FP + ks * 16 + colb8) * 2;
                LDMX4(b0, b1, b2, b3, kbl + off);
                MMA4(sacc[2 * g],     fqh[ks], b0, b1);
                MMA4(sacc[2 * g + 1], fqh[ks], b2, b3);
            }
        }

        // ---- causal mask (tiles at/past diagonal)
        const int grow0 = qrow0 + wid * 16 + (lane >> 2);
        if (kb >= 2 * qb) {
#pragma unroll
            for (int f = 0; f < 8; f++) {
                int c = kb * 64 + f * 8 + 2 * (lane & 3);
                if (c     > grow0)     sacc[f][0] += NEG_;
                if (c + 1 > grow0)     sacc[f][1] += NEG_;
                if (c     > grow0 + 8) sacc[f][2] += NEG_;
                if (c + 1 > grow0 + 8) sacc[f][3] += NEG_;
            }
        }

        // ---- online softmax (rows r0 = grow0, r1 = grow0+8)
        float mx0 = -1e30f, mx1 = -1e30f;
#pragma unroll
        for (int f = 0; f < 8; f++) {
            mx0 = fmaxf(mx0, fmaxf(sacc[f][0], sacc[f][1]));
            mx1 = fmaxf(mx1, fmaxf(sacc[f][2], sacc[f][3]));
        }
        mx0 = fmaxf(mx0, __shfl_xor_sync(0xffffffffu, mx0, 1));
        mx0 = fmaxf(mx0, __shfl_xor_sync(0xffffffffu, mx0, 2));
        mx1 = fmaxf(mx1, __shfl_xor_sync(0xffffffffu, mx1, 1));
        mx1 = fmaxf(mx1, __shfl_xor_sync(0xffffffffu, mx1, 2));
        float mn0 = fmaxf(m0, mx0), mn1 = fmaxf(m1, mx1);
        float a0 = __expf(m0 - mn0), a1 = __expf(m1 - mn1);
        m0 = mn0; m1 = mn1;
        float rs0 = 0.0f, rs1 = 0.0f;
#pragma unroll
        for (int f = 0; f < 8; f++) {
            sacc[f][0] = __expf(sacc[f][0] - mn0);
            sacc[f][1] = __expf(sacc[f][1] - mn0);
            sacc[f][2] = __expf(sacc[f][2] - mn1);
            sacc[f][3] = __expf(sacc[f][3] - mn1);
            rs0 += sacc[f][0] + sacc[f][1];
            rs1 += sacc[f][2] + sacc[f][3];
        }
        rs0 += __shfl_xor_sync(0xffffffffu, rs0, 1);
        rs0 += __shfl_xor_sync(0xffffffffu, rs0, 2);
        rs1 += __shfl_xor_sync(0xffffffffu, rs1, 1);
        rs1 += __shfl_xor_sync(0xffffffffu, rs1, 2);
        l0 = l0 * a0 + rs0;
        l1 = l1 * a1 + rs1;
#pragma unroll
        for (int f = 0; f < 8; f++) {
            oacc[f][0] *= a0; oacc[f][1] *= a0;
            oacc[f][2] *= a1; oacc[f][3] *= a1;
        }

        // ---- P: C-frags -> A-frags (hi/lo), registers only
        uint32_t ph[4][4], pl[4][4];
#pragma unroll
        for (int js = 0; js < 4; js++) {
            split_pack(sacc[2 * js][0],     sacc[2 * js][1],     ph[js][0], pl[js][0]);
            split_pack(sacc[2 * js][2],     sacc[2 * js][3],     ph[js][1], pl[js][1]);
            split_pack(sacc[2 * js + 1][0], sacc[2 * js + 1][1], ph[js][2], pl[js][2]);
            split_pack(sacc[2 * js + 1][2], sacc[2 * js + 1][3], ph[js][3], pl[js][3]);
        }

        // ---- O += P.V with 3-way split
        uint32_t vbh = smem_u32(sV + (buf * 2 + 0) * 64 * FP);
        uint32_t vbl = smem_u32(sV + (buf * 2 + 1) * 64 * FP);
#pragma unroll
        for (int js = 0; js < 4; js++) {
#pragma unroll
            for (int g = 0; g < 4; g++) {
                uint32_t b0, b1, b2, b3;
                uint32_t off = ((16 * g + rowb) * FP + js * 16 + colb8) * 2;
                LDMX4(b0, b1, b2, b3, vbh + off);
                MMA4(oacc[2 * g],     ph[js], b0, b1);
                MMA4(oacc[2 * g + 1], ph[js], b2, b3);
                MMA4(oacc[2 * g],     pl[js], b0, b1);
                MMA4(oacc[2 * g + 1], pl[js], b2, b3);
            }
        }
#pragma unroll
        for (int js = 0; js < 4; js++) {
#pragma unroll
            for (int g = 0; g < 4; g++) {
                uint32_t b0, b1, b2, b3;
                uint32_t off = ((16 * g + rowb) * FP + js * 16 + colb8) * 2;
                LDMX4(b0, b1, b2, b3, vbl + off);
                MMA4(oacc[2 * g],     ph[js], b0, b1);
                MMA4(oacc[2 * g + 1], ph[js], b2, b3);
            }
        }
        __syncthreads();   // all warps done with buf before it is refilled
    }

    // ---- epilogue
    const int grow0 = qrow0 + wid * 16 + (lane >> 2);
    float inv0 = 1.0f / l0, inv1 = 1.0f / l1;
    float* ob = o + ((size_t)(b * N_ + grow0)) * D_ + h * HD_;
#pragma unroll
    for (int f = 0; f < 8; f++) {
        int dcol = f * 8 + 2 * (lane & 3);
        *(float2*)(ob + dcol) =
            make_float2(oacc[f][0] * inv0, oacc[f][1] * inv0);
        *(float2*)(ob + 8 * D_ + dcol) =
            make_float2(oacc[f][2] * inv1, oacc[f][3] * inv1);
    }
}

// ---------------------------------------------------------------------------
extern "C" void kernel_launch(void* const* d_in, const int* in_sizes, int n_in,
                              void* d_out, int out_size)
{
    const float* x  = (const float*)d_in[0];
    const float* Wq = (const float*)d_in[1];
    const float* Wk = (const float*)d_in[2];
    const float* Wv = (const float*)d_in[3];
    const float* Wo = (const float*)d_in[4];
    const float* bo = (const float*)d_in[5];
    float* out = (float*)d_out;

    float *q, *k, *v, *o;
    __nv_bfloat16 *x2, *o2, *wq2, *wk2, *wv2, *wo2;
    __nv_bfloat16 *qh, *ql, *kh, *kl, *vth, *vtl;
    cudaGetSymbolAddress((void**)&q, g_q);
    cudaGetSymbolAddress((void**)&k, g_k);
    cudaGetSymbolAddress((void**)&v, g_v);
    cudaGetSymbolAddress((void**)&o, g_o);
    cudaGetSymbolAddress((void**)&x2, g_x2);
    cudaGetSymbolAddress((void**)&o2, g_o2);
    cudaGetSymbolAddress((void**)&wq2, g_wq2);
    cudaGetSymbolAddress((void**)&wk2, g_wk2);
    cudaGetSymbolAddress((void**)&wv2, g_wv2);
    cudaGetSymbolAddress((void**)&wo2, g_wo2);
    cudaGetSymbolAddress((void**)&qh, g_qh);
    cudaGetSymbolAddress((void**)&ql, g_ql);
    cudaGetSymbolAddress((void**)&kh, g_kh);
    cudaGetSymbolAddress((void**)&kl, g_kl);
    cudaGetSymbolAddress((void**)&vth, g_vth);
    cudaGetSymbolAddress((void**)&vtl, g_vtl);

    cudaFuncSetAttribute(flash_mma, cudaFuncAttributeMaxDynamicSharedMemorySize,
                         (int)FL_SMEM);

    build_cs_kernel<<<(N_ * 32 + 255) / 256, 256>>>();

    int xthreads = M_ * (D_ / 4);
    int wthreads = D_ * (D_ / 4);
    split_kernel<<<(xthreads + 255) / 256, 256>>>(x, x2, M_, 0);
    split_kernel<<<(wthreads + 255) / 256, 256>>>(Wq, wq2, D_, 1);
    split_kernel<<<(wthreads + 255) / 256, 256>>>(Wk, wk2, D_, 1);
    split_kernel<<<(wthreads + 255) / 256, 256>>>(Wv, wv2, D_, 1);
    split_kernel<<<(wthreads + 255) / 256, 256>>>(Wo, wo2, D_, 1);

    dim3 ggrid(D_ / 128, M_ / 128);   // (8, 64)
    mm_mma<<<ggrid, 256>>>(x2, wq2, nullptr, q);
    mm_mma<<<ggrid, 256>>>(x2, wk2, nullptr, k);
    mm_mma<<<ggrid, 256>>>(x2, wv2, nullptr, v);

    int rpairs = M_ * 512;
    rope_split_kernel<<<(rpairs + 255) / 256, 256>>>(q, k, qh, ql, kh, kl);
    dim3 vgrid(N_ / 64, H_, B_);
    v_split_t_kernel<<<vgrid, 256>>>(v, vth, vtl);

    dim3 fgrid(N_ / 128, H_, B_);     // (16, 16, 4)
    flash_mma<<<fgrid, 256, FL_SMEM>>>(qh, ql, kh, kl, vth, vtl, o);

    split_kernel<<<(xthreads + 255) / 256, 256>>>(o, o2, M_, 0);
    mm_mma<<<ggrid, 256>>>(o2, wo2, bo, out);
}

// round 7
// speedup vs baseline: 4.3771x; 1.1350x over previous
#include <cuda_runtime.h>
#include <cuda_bf16.h>
#include <math.h>
#include <cstdint>

// Problem constants
#define B_ 4
#define N_ 2048
#define D_ 1024
#define H_ 16
#define HD_ 64
#define M_ (B_ * N_)          // 8192 rows
#define K3_ (3 * D_)          // 3072: [hi|lo|hi] x [hi|hi|lo] split concat
#define SCALE_ (1.0f / 64.0f)
#define NEG_ (-10000.0f)

// Scratch (static device globals — no runtime allocation allowed)
__device__ float g_q[M_ * D_];
__device__ float g_k[M_ * D_];
__device__ float g_v[M_ * D_];
__device__ float g_o[M_ * D_];
__device__ float2 g_cs[N_ * 32];                  // RoPE cos/sin table
__device__ __nv_bfloat16 g_x2[(size_t)M_ * K3_];  // x split [hi|lo|hi]
__device__ __nv_bfloat16 g_o2[(size_t)M_ * K3_];  // o split [hi|lo|hi]
__device__ __nv_bfloat16 g_wqkv[(size_t)(3 * D_) * K3_]; // Wq|Wk|Wv splits [hi|hi|lo]
__device__ __nv_bfloat16 g_wo2[(size_t)D_ * K3_];
// flash operands: hi/lo bf16, Q pre-scaled; V transposed per (b,h)
__device__ __nv_bfloat16 g_qh[(size_t)M_ * D_];
__device__ __nv_bfloat16 g_ql[(size_t)M_ * D_];
__device__ __nv_bfloat16 g_kh[(size_t)M_ * D_];
__device__ __nv_bfloat16 g_kl[(size_t)M_ * D_];
__device__ __nv_bfloat16 g_vth[(size_t)B_ * H_ * HD_ * N_];
__device__ __nv_bfloat16 g_vtl[(size_t)B_ * H_ * HD_ * N_];

__device__ __forceinline__ uint32_t smem_u32(const void* p) {
    uint32_t a;
    asm("{ .reg .u64 t; cvta.to.shared.u64 t, %1; cvt.u32.u64 %0, t; }"
        : "=r"(a) : "l"(p));
    return a;
}

#define CP16(dst, src) \
    asm volatile("cp.async.cg.shared.global [%0], [%1], 16;" :: "r"(dst), "l"(src))
#define LDMX4(r0, r1, r2, r3, addr) \
    asm volatile("ldmatrix.sync.aligned.m8n8.x4.shared.b16 {%0,%1,%2,%3}, [%4];" \
                 : "=r"(r0), "=r"(r1), "=r"(r2), "=r"(r3) : "r"(addr))
#define MMA4(dd, aa, b0, b1) \
    asm volatile("mma.sync.aligned.m16n8k16.row.col.f32.bf16.bf16.f32 " \
                 "{%0,%1,%2,%3}, {%4,%5,%6,%7}, {%8,%9}, {%0,%1,%2,%3};" \
                 : "+f"((dd)[0]), "+f"((dd)[1]), "+f"((dd)[2]), "+f"((dd)[3]) \
                 : "r"((aa)[0]), "r"((aa)[1]), "r"((aa)[2]), "r"((aa)[3]), \
                   "r"(b0), "r"(b1))

__device__ __forceinline__ void split_pack(float x, float y, uint32_t& hi, uint32_t& lo) {
    __nv_bfloat16 hx = __float2bfloat16(x), hy = __float2bfloat16(y);
    __nv_bfloat16 lx = __float2bfloat16(x - __bfloat162float(hx));
    __nv_bfloat16 ly = __float2bfloat16(y - __bfloat162float(hy));
    __nv_bfloat162 Hh{hx, hy}, Ll{lx, ly};
    hi = *(uint32_t*)&Hh;
    lo = *(uint32_t*)&Ll;
}

// ===========================================================================
// hi/lo bf16 split with 3-way concat (for projection GEMMs).
// wmode=0 (activations): [hi | lo | hi];  wmode=1 (weights): [hi | hi | lo]
// ===========================================================================
__global__ void split_kernel(const float* __restrict__ src,
                             __nv_bfloat16* __restrict__ dst, int rows, int wmode)
{
    int gid = blockIdx.x * blockDim.x + threadIdx.x;
    int total = rows * (D_ / 4);
    if (gid >= total) return;
    int r = gid >> 8;
    int c4 = gid & 255;
    float4 xv = ((const float4*)src)[gid];
    float xs[4] = {xv.x, xv.y, xv.z, xv.w};
    __nv_bfloat162 hi2[2], lo2[2];
#pragma unroll
    for (int j = 0; j < 2; j++) {
        __nv_bfloat16 h0 = __float2bfloat16(xs[2 * j]);
        __nv_bfloat16 h1 = __float2bfloat16(xs[2 * j + 1]);
        __nv_bfloat16 l0 = __float2bfloat16(xs[2 * j] - __bfloat162float(h0));
        __nv_bfloat16 l1 = __float2bfloat16(xs[2 * j + 1] - __bfloat162float(h1));
        hi2[j] = __nv_bfloat162{h0, h1};
        lo2[j] = __nv_bfloat162{l0, l1};
    }
    __nv_bfloat162* d0 = (__nv_bfloat162*)(dst + (size_t)r * K3_) + c4 * 2;
    __nv_bfloat162* d1 = (__nv_bfloat162*)(dst + (size_t)r * K3_ + D_) + c4 * 2;
    __nv_bfloat162* d2 = (__nv_bfloat162*)(dst + (size_t)r * K3_ + 2 * D_) + c4 * 2;
    d0[0] = hi2[0]; d0[1] = hi2[1];
    if (wmode) { d1[0] = hi2[0]; d1[1] = hi2[1]; d2[0] = lo2[0]; d2[1] = lo2[1]; }
    else       { d1[0] = lo2[0]; d1[1] = lo2[1]; d2[0] = hi2[0]; d2[1] = hi2[1]; }
}

// ===========================================================================
// mma.sync bf16 GEMM, 4-stage cp.async pipeline, fused multi-output.
// C[bn] routed: bn<1024 -> C0, <2048 -> C1, else C2 (col = bn & 1023).
// A [rows x 3072], Bw [ncols x 3072] row-major. One __syncthreads per chunk.
// ===========================================================================
#define BK 32
#define PITCH 40
#define TILE_ELEMS (128 * PITCH)         // one operand per stage
#define STAGE_ELEMS (2 * TILE_ELEMS)     // A then B
#define ST 4
#define MM_SMEM (ST * STAGE_ELEMS * 2)   // bytes

__global__ __launch_bounds__(256) void mm_mma(
    const __nv_bfloat16* __restrict__ A, const __nv_bfloat16* __restrict__ Bw,
    const float* __restrict__ bias,
    float* __restrict__ C0, float* __restrict__ C1, float* __restrict__ C2)
{
    extern __shared__ __nv_bfloat16 dsm[];

    const int tid  = threadIdx.x;
    const int lane = tid & 31;
    const int wid  = tid >> 5;
    const int wm   = wid >> 2;
    const int wn   = wid & 3;
    const int bm   = blockIdx.y * 128;
    const int bn   = blockIdx.x * 128;

    const uint32_t base = smem_u32(dsm);

    const uint32_t aRow = (uint32_t)(lane & 15);
    const uint32_t aKof = (uint32_t)((lane >> 4) << 3);
    const uint32_t bRow = (uint32_t)(lane & 7);
    const uint32_t bKof = (uint32_t)(((lane >> 3) & 1) << 3);

    float d[4][4][4];
#pragma unroll
    for (int mi = 0; mi < 4; mi++)
#pragma unroll
        for (int ni = 0; ni < 4; ni++)
#pragma unroll
            for (int r = 0; r < 4; r++) d[mi][ni][r] = 0.0f;

    const int NC = K3_ / BK;    // 96 chunks

    // each thread: 2 A-segs + 2 B-segs per chunk
    const int lrow = tid >> 2;            // shared by both halves
    const int lseg = tid & 3;

    auto load_chunk = [&](int c, int stage) {
        uint32_t sA = base + (uint32_t)(stage * STAGE_ELEMS) * 2;
        uint32_t sB = sA + (uint32_t)TILE_ELEMS * 2;
#pragma unroll
        for (int t = 0; t < 2; t++) {
            int row = lrow + t * 64;
            uint32_t dA = sA + (uint32_t)(row * PITCH * 2 + lseg * 16);
            uint32_t dB = sB + (uint32_t)(row * PITCH * 2 + lseg * 16);
            const __nv_bfloat16* gA = A  + (size_t)(bm + row) * K3_ + c * BK + lseg * 8;
            const __nv_bfloat16* gB = Bw + (size_t)(bn + row) * K3_ + c * BK + lseg * 8;
            CP16(dA, gA);
            CP16(dB, gB);
        }
        asm volatile("cp.async.commit_group;");
    };

    // prologue: stages 0..ST-2
#pragma unroll
    for (int s = 0; s < ST - 1; s++) load_chunk(s, s);

    for (int c = 0; c < NC; c++) {
        asm volatile("cp.async.wait_group %0;" :: "n"(ST - 2));
        __syncthreads();

        // issue load for chunk c+ST-1 into the stage freed last iteration
        if (c + ST - 1 < NC) load_chunk(c + ST - 1, (c + ST - 1) % ST);
        else asm volatile("cp.async.commit_group;");   // keep group count

        const int stage = c % ST;
        uint32_t sA = base + (uint32_t)(stage * STAGE_ELEMS) * 2;
        uint32_t sB = sA + (uint32_t)TILE_ELEMS * 2;

#pragma unroll
        for (int ks = 0; ks < 2; ks++) {
            uint32_t a[4][4], b[4][2];
#pragma unroll
            for (int mi = 0; mi < 4; mi++) {
                uint32_t addr = sA +
                    ((uint32_t)(wm * 64 + mi * 16) + aRow) * (PITCH * 2) +
                    ((uint32_t)(ks * 16) + aKof) * 2;
                LDMX4(a[mi][0], a[mi][1], a[mi][2], a[mi][3], addr);
            }
#pragma unroll
            for (int ni = 0; ni < 4; ni++) {
                uint32_t addr = sB +
                    ((uint32_t)(wn * 32 + ni * 8) + bRow) * (PITCH * 2) +
                    ((uint32_t)(ks * 16) + bKof) * 2;
                asm volatile(
                    "ldmatrix.sync.aligned.m8n8.x2.shared.b16 {%0,%1}, [%2];"
                    : "=r"(b[ni][0]), "=r"(b[ni][1]) : "r"(addr));
            }
#pragma unroll
            for (int mi = 0; mi < 4; mi++)
#pragma unroll
                for (int ni = 0; ni < 4; ni++)
                    MMA4(d[mi][ni], a[mi], b[ni][0], b[ni][1]);
        }
    }

    // epilogue: route output by bn
    float* Cs = (bn < 1024) ? C0 : (bn < 2048) ? C1 : C2;
    const int cbase = bn & 1023;
#pragma unroll
    for (int mi = 0; mi < 4; mi++) {
        int r0 = bm + wm * 64 + mi * 16 + (lane >> 2);
#pragma unroll
        for (int ni = 0; ni < 4; ni++) {
            int cc = cbase + wn * 32 + ni * 8 + ((lane & 3) << 1);
            float b0 = bias ? bias[cc] : 0.0f;
            float b1 = bias ? bias[cc + 1] : 0.0f;
            *(float2*)&Cs[(size_t)r0 * D_ + cc] =
                make_float2(d[mi][ni][0] + b0, d[mi][ni][1] + b1);
            *(float2*)&Cs[(size_t)(r0 + 8) * D_ + cc] =
                make_float2(d[mi][ni][2] + b0, d[mi][ni][3] + b1);
        }
    }
}

// ===========================================================================
// RoPE cos/sin table build
// ===========================================================================
__global__ void build_cs_kernel()
{
    int gid = blockIdx.x * blockDim.x + threadIdx.x;
    if (gid >= N_ * 32) return;
    int pos = gid >> 5;
    int i   = gid & 31;
    float inv_f = (float)pow(10000.0, -(double)(2 * i) / 64.0);
    float ang   = (float)pos * inv_f;
    g_cs[gid] = make_float2((float)cos((double)ang), (float)sin((double)ang));
}

// ===========================================================================
// Fused RoPE + hi/lo split for Q (pre-scaled) and K.
// ===========================================================================
__global__ void rope_split_kernel(
    const float* __restrict__ q, const float* __restrict__ k,
    __nv_bfloat16* __restrict__ qh, __nv_bfloat16* __restrict__ ql,
    __nv_bfloat16* __restrict__ kh, __nv_bfloat16* __restrict__ kl)
{
    int gid = blockIdx.x * blockDim.x + threadIdx.x;
    if (gid >= M_ * 512) return;
    int row = gid >> 9;
    int p   = gid & 511;
    int i   = p & 31;
    int pos = row & (N_ - 1);
    float2 cs = g_cs[pos * 32 + i];

    float2 xq = ((const float2*)(q + (size_t)row * D_))[p];
    float qa = fmaf(xq.x, cs.x, -xq.y * cs.y) * SCALE_;
    float qb = fmaf(xq.y, cs.x,  xq.x * cs.y) * SCALE_;
    uint32_t qhi, qlo;
    split_pack(qa, qb, qhi, qlo);
    ((uint32_t*)(qh + (size_t)row * D_))[p] = qhi;
    ((uint32_t*)(ql + (size_t)row * D_))[p] = qlo;

    float2 xk = ((const float2*)(k + (size_t)row * D_))[p];
    float ka = fmaf(xk.x, cs.x, -xk.y * cs.y);
    float kb = fmaf(xk.y, cs.x,  xk.x * cs.y);
    uint32_t khi, klo;
    split_pack(ka, kb, khi, klo);
    ((uint32_t*)(kh + (size_t)row * D_))[p] = khi;
    ((uint32_t*)(kl + (size_t)row * D_))[p] = klo;
}

// ===========================================================================
// V split + transpose: v [b,n,h*64+d] f32 -> vth/vtl [b,h,d,n] bf16
// ===========================================================================
__global__ void v_split_t_kernel(const float* __restrict__ v,
                                 __nv_bfloat16* __restrict__ vth,
                                 __nv_bfloat16* __restrict__ vtl)
{
    __shared__ float tile[64][65];
    int n0 = blockIdx.x * 64, hh = blockIdx.y, b = blockIdx.z;
    int tid = threadIdx.x;
#pragma unroll
    for (int i = 0; i < 16; i++) {
        int idx = tid + i * 256;
        int r = idx >> 6, c = idx & 63;
        tile[r][c] = v[((size_t)(b * N_ + n0 + r)) * D_ + hh * HD_ + c];
    }
    __syncthreads();
#pragma unroll
    for (int i = 0; i < 16; i++) {
        int idx = tid + i * 256;
        int dd = idx >> 6, c = idx & 63;
        float val = tile[c][dd];
        __nv_bfloat16 hv = __float2bfloat16(val);
        __nv_bfloat16 lv = __float2bfloat16(val - __bfloat162float(hv));
        size_t off = ((size_t)((b * H_ + hh) * HD_ + dd)) * N_ + n0 + c;
        vth[off] = hv;
        vtl[off] = lv;
    }
}

// ===========================================================================
// Tensor-core causal flash attention with hi/lo split (unchanged).
// ===========================================================================
#define FP 72
#define FL_SMEM ((256 * FP + 2 * 2 * 64 * FP + 2 * 2 * 64 * FP) * 2)

__global__ __launch_bounds__(256, 1) void flash_mma(
    const __nv_bfloat16* __restrict__ qh, const __nv_bfloat16* __restrict__ ql,
    const __nv_bfloat16* __restrict__ kh, const __nv_bfloat16* __restrict__ kl,
    const __nv_bfloat16* __restrict__ vth, const __nv_bfloat16* __restrict__ vtl,
    float* __restrict__ o)
{
    extern __shared__ __nv_bfloat16 sm[];
    __nv_bfloat16* sQh = sm;
    __nv_bfloat16* sQl = sm + 128 * FP;
    __nv_bfloat16* sK  = sm + 256 * FP;
    __nv_bfloat16* sV  = sm + 256 * FP + 4 * 64 * FP;

    const int tid = threadIdx.x, lane = tid & 31, wid = tid >> 5;
    const int qb = blockIdx.x, h = blockIdx.y, b = blockIdx.z;
    const int qrow0 = qb * 128;

    {
#pragma unroll
        for (int i = 0; i < 8; i++) {
            int t = tid + i * 256;
            int tensor = t >> 10;
            int rem = t & 1023;
            int r = rem >> 3, s = rem & 7;
            uint32_t dst = smem_u32((tensor ? sQl : sQh) + r * FP) + s * 16;
            const __nv_bfloat16* src = (tensor ? ql : qh) +
                ((size_t)(b * N_ + qrow0 + r)) * D_ + h * HD_ + s * 8;
            CP16(dst, src);
        }
        asm volatile("cp.async.commit_group;");
    }

    auto load_kv = [&](int kb, int buf) {
#pragma unroll
        for (int i = 0; i < 8; i++) {
            int t = tid + i * 256;
            int tensor = t >> 9;
            int rem = t & 511;
            int r = rem >> 3, s = rem & 7;
            uint32_t dst;
            const __nv_bfloat16* src;
            if (tensor < 2) {
                dst = smem_u32(sK + ((buf * 2 + tensor) * 64 + r) * FP) + s * 16;
                src = (tensor ? kl : kh) +
                    ((size_t)(b * N_ + kb * 64 + r)) * D_ + h * HD_ + s * 8;
            } else {
                dst = smem_u32(sV + ((buf * 2 + (tensor - 2)) * 64 + r) * FP) + s * 16;
                src = ((tensor == 3) ? vtl : vth) +
                    ((size_t)((b * H_ + h) * HD_ + r)) * N_ + kb * 64 + s * 8;
            }
            CP16(dst, src);
        }
        asm volatile("cp.async.commit_group;");
    };

    load_kv(0, 0);
    asm volatile("cp.async.wait_group 0;");
    __syncthreads();

    uint32_t fqh[4][4], fql[4][4];
    {
        uint32_t rowa = (uint32_t)(wid * 16 + (lane & 15));
        uint32_t cola = (uint32_t)(((lane >> 4) & 1) * 8);
        uint32_t bqh = smem_u32(sQh), bql = smem_u32(sQl);
#pragma unroll
        for (int ks = 0; ks < 4; ks++) {
            uint32_t off = (rowa * FP + ks * 16 + cola) * 2;
            LDMX4(fqh[ks][0], fqh[ks][1], fqh[ks][2], fqh[ks][3], bqh + off);
            LDMX4(fql[ks][0], fql[ks][1], fql[ks][2], fql[ks][3], bql + off);
        }
    }

    float m0 = -1e30f, m1 = -1e30f, l0 = 0.0f, l1 = 0.0f;
    float oacc[8][4];
#pragma unroll
    for (int f = 0; f < 8; f++)
#pragma unroll
        for (int r = 0; r < 4; r++) oacc[f][r] = 0.0f;

    const uint32_t rowb = (uint32_t)((lane & 7) + ((lane >> 4) & 1) * 8);
    const uint32_t colb8 = (uint32_t)(((lane >> 3) & 1) * 8);
    const int kbmax = 2 * qb + 1;

    for (int kb = 0; kb <= kbmax; kb++) {
        const int buf = kb & 1;
        if (kb) {
            asm volatile("cp.async.wait_group 0;");
            __syncthreads();
        }
        if (kb < kbmax) load_kv(kb + 1, buf ^ 1);

        float sacc[8][4];
#pragma unroll
        for (int f = 0; f < 8; f++)
#pragma unroll
            for (int r = 0; r < 4; r++) sacc[f][r] = 0.0f;

        uint32_t kbh = smem_u32(sK + (buf * 2 + 0) * 64 * FP);
        uint32_t kbl = smem_u32(sK + (buf * 2 + 1) * 64 * FP);
#pragma unroll
        for (int ks = 0; ks < 4; ks++) {
#pragma unroll
            for (int g = 0; g < 4; g++) {
                uint32_t b0, b1, b2, b3;
                uint32_t off = ((16 * g + rowb) * FP + ks * 16 + colb8) * 2;
                LDMX4(b0, b1, b2, b3, kbh + off);
                MMA4(sacc[2 * g],     fqh[ks], b0, b1);
                MMA4(sacc[2 * g + 1], fqh[ks], b2, b3);
                MMA4(sacc[2 * g],     fql[ks], b0, b1);
                MMA4(sacc[2 * g + 1], fql[ks], b2, b3);
            }
        }
#pragma unroll
        for (int ks = 0; ks < 4; ks++) {
#pragma unroll
            for (int g = 0; g < 4; g++) {
                uint32_t b0, b1, b2, b3;
                uint32_t off = ((16 * g + rowb) * FP + ks * 16 + colb8) * 2;
                LDMX4(b0, b1, b2, b3, kbl + off);
                MMA4(sacc[2 * g],     fqh[ks], b0, b1);
                MMA4(sacc[2 * g + 1], fqh[ks], b2, b3);
            }
        }

        const int grow0 = qrow0 + wid * 16 + (lane >> 2);
        if (kb >= 2 * qb) {
#pragma unroll
            for (int f = 0; f < 8; f++) {
                int c = kb * 64 + f * 8 + 2 * (lane & 3);
                if (c     > grow0)     sacc[f][0] += NEG_;
                if (c + 1 > grow0)     sacc[f][1] += NEG_;
                if (c     > grow0 + 8) sacc[f][2] += NEG_;
                if (c + 1 > grow0 + 8) sacc[f][3] += NEG_;
            }
        }

        float mx0 = -1e30f, mx1 = -1e30f;
#pragma unroll
        for (int f = 0; f < 8; f++) {
            mx0 = fmaxf(mx0, fmaxf(sacc[f][0], sacc[f][1]));
            mx1 = fmaxf(mx1, fmaxf(sacc[f][2], sacc[f][3]));
        }
        mx0 = fmaxf(mx0, __shfl_xor_sync(0xffffffffu, mx0, 1));
        mx0 = fmaxf(mx0, __shfl_xor_sync(0xffffffffu, mx0, 2));
        mx1 = fmaxf(mx1, __shfl_xor_sync(0xffffffffu, mx1, 1));
        mx1 = fmaxf(mx1, __shfl_xor_sync(0xffffffffu, mx1, 2));
        float mn0 = fmaxf(m0, mx0), mn1 = fmaxf(m1, mx1);
        float a0 = __expf(m0 - mn0), a1 = __expf(m1 - mn1);
        m0 = mn0; m1 = mn1;
        float rs0 = 0.0f, rs1 = 0.0f;
#pragma unroll
        for (int f = 0; f < 8; f++) {
            sacc[f][0] = __expf(sacc[f][0] - mn0);
            sacc[f][1] = __expf(sacc[f][1] - mn0);
            sacc[f][2] = __expf(sacc[f][2] - mn1);
            sacc[f][3] = __expf(sacc[f][3] - mn1);
            rs0 += sacc[f][0] + sacc[f][1];
            rs1 += sacc[f][2] + sacc[f][3];
        }
        rs0 += __shfl_xor_sync(0xffffffffu, rs0, 1);
        rs0 += __shfl_xor_sync(0xffffffffu, rs0, 2);
        rs1 += __shfl_xor_sync(0xffffffffu, rs1, 1);
        rs1 += __shfl_xor_sync(0xffffffffu, rs1, 2);
        l0 = l0 * a0 + rs0;
        l1 = l1 * a1 + rs1;
#pragma unroll
        for (int f = 0; f < 8; f++) {
            oacc[f][0] *= a0; oacc[f][1] *= a0;
            oacc[f][2] *= a1; oacc[f][3] *= a1;
        }

        uint32_t ph[4][4], pl[4][4];
#pragma unroll
        for (int js = 0; js < 4; js++) {
            split_pack(sacc[2 * js][0],     sacc[2 * js][1],     ph[js][0], pl[js][0]);
            split_pack(sacc[2 * js][2],     sacc[2 * js][3],     ph[js][1], pl[js][1]);
            split_pack(sacc[2 * js + 1][0], sacc[2 * js + 1][1], ph[js][2], pl[js][2]);
            split_pack(sacc[2 * js + 1][2], sacc[2 * js + 1][3], ph[js][3], pl[js][3]);
        }

        uint32_t vbh = smem_u32(sV + (buf * 2 + 0) * 64 * FP);
        uint32_t vbl = smem_u32(sV + (buf * 2 + 1) * 64 * FP);
#pragma unroll
        for (int js = 0; js < 4; js++) {
#pragma unroll
            for (int g = 0; g < 4; g++) {
                uint32_t b0, b1, b2, b3;
                uint32_t off = ((16 * g + rowb) * FP + js * 16 + colb8) * 2;
                LDMX4(b0, b1, b2, b3, vbh + off);
                MMA4(oacc[2 * g],     ph[js], b0, b1);
                MMA4(oacc[2 * g + 1], ph[js], b2, b3);
                MMA4(oacc[2 * g],     pl[js], b0, b1);
                MMA4(oacc[2 * g + 1], pl[js], b2, b3);
            }
        }
#pragma unroll
        for (int js = 0; js < 4; js++) {
#pragma unroll
            for (int g = 0; g < 4; g++) {
                uint32_t b0, b1, b2, b3;
                uint32_t off = ((16 * g + rowb) * FP + js * 16 + colb8) * 2;
                LDMX4(b0, b1, b2, b3, vbl + off);
                MMA4(oacc[2 * g],     ph[js], b0, b1);
                MMA4(oacc[2 * g + 1], ph[js], b2, b3);
            }
        }
        __syncthreads();
    }

    const int grow0 = qrow0 + wid * 16 + (lane >> 2);
    float inv0 = 1.0f / l0, inv1 = 1.0f / l1;
    float* ob = o + ((size_t)(b * N_ + grow0)) * D_ + h * HD_;
#pragma unroll
    for (int f = 0; f < 8; f++) {
        int dcol = f * 8 + 2 * (lane & 3);
        *(float2*)(ob + dcol) =
            make_float2(oacc[f][0] * inv0, oacc[f][1] * inv0);
        *(float2*)(ob + 8 * D_ + dcol) =
            make_float2(oacc[f][2] * inv1, oacc[f][3] * inv1);
    }
}

// ---------------------------------------------------------------------------
extern "C" void kernel_launch(void* const* d_in, const int* in_sizes, int n_in,
                              void* d_out, int out_size)
{
    const float* x  = (const float*)d_in[0];
    const float* Wq = (const float*)d_in[1];
    const float* Wk = (const float*)d_in[2];
    const float* Wv = (const float*)d_in[3];
    const float* Wo = (const float*)d_in[4];
    const float* bo = (const float*)d_in[5];
    float* out = (float*)d_out;

    float *q, *k, *v, *o;
    __nv_bfloat16 *x2, *o2, *wqkv, *wo2;
    __nv_bfloat16 *qh, *ql, *kh, *kl, *vth, *vtl;
    cudaGetSymbolAddress((void**)&q, g_q);
    cudaGetSymbolAddress((void**)&k, g_k);
    cudaGetSymbolAddress((void**)&v, g_v);
    cudaGetSymbolAddress((void**)&o, g_o);
    cudaGetSymbolAddress((void**)&x2, g_x2);
    cudaGetSymbolAddress((void**)&o2, g_o2);
    cudaGetSymbolAddress((void**)&wqkv, g_wqkv);
    cudaGetSymbolAddress((void**)&wo2, g_wo2);
    cudaGetSymbolAddress((void**)&qh, g_qh);
    cudaGetSymbolAddress((void**)&ql, g_ql);
    cudaGetSymbolAddress((void**)&kh, g_kh);
    cudaGetSymbolAddress((void**)&kl, g_kl);
    cudaGetSymbolAddress((void**)&vth, g_vth);
    cudaGetSymbolAddress((void**)&vtl, g_vtl);

    cudaFuncSetAttribute(flash_mma, cudaFuncAttributeMaxDynamicSharedMemorySize,
                         (int)FL_SMEM);
    cudaFuncSetAttribute(mm_mma, cudaFuncAttributeMaxDynamicSharedMemorySize,
                         (int)MM_SMEM);

    build_cs_kernel<<<(N_ * 32 + 255) / 256, 256>>>();

    int xthreads = M_ * (D_ / 4);
    int wthreads = D_ * (D_ / 4);
    split_kernel<<<(xthreads + 255) / 256, 256>>>(x, x2, M_, 0);
    split_kernel<<<(wthreads + 255) / 256, 256>>>(Wq, wqkv, D_, 1);
    split_kernel<<<(wthreads + 255) / 256, 256>>>(Wk, wqkv + (size_t)D_ * K3_, D_, 1);
    split_kernel<<<(wthreads + 255) / 256, 256>>>(Wv, wqkv + (size_t)2 * D_ * K3_, D_, 1);
    split_kernel<<<(wthreads + 255) / 256, 256>>>(Wo, wo2, D_, 1);

    // fused QKV projection
    dim3 qkvgrid(3 * D_ / 128, M_ / 128);  // (24, 64)
    mm_mma<<<qkvgrid, 256, MM_SMEM>>>(x2, wqkv, nullptr, q, k, v);

    int rpairs = M_ * 512;
    rope_split_kernel<<<(rpairs + 255) / 256, 256>>>(q, k, qh, ql, kh, kl);
    dim3 vgrid(N_ / 64, H_, B_);
    v_split_t_kernel<<<vgrid, 256>>>(v, vth, vtl);

    dim3 fgrid(N_ / 128, H_, B_);     // (16, 16, 4)
    flash_mma<<<fgrid, 256, FL_SMEM>>>(qh, ql, kh, kl, vth, vtl, o);

    split_kernel<<<(xthreads + 255) / 256, 256>>>(o, o2, M_, 0);
    dim3 ogrid(D_ / 128, M_ / 128);   // (8, 64)
    mm_mma<<<ogrid, 256, MM_SMEM>>>(o2, wo2, bo, out, nullptr, nullptr);
}

// round 8
// speedup vs baseline: 4.3972x; 1.0046x over previous
#include <cuda_runtime.h>
#include <cuda_bf16.h>
#include <math.h>
#include <cstdint>

// Problem constants
#define B_ 4
#define N_ 2048
#define D_ 1024
#define H_ 16
#define HD_ 64
#define M_ (B_ * N_)          // 8192 rows
#define K3_ (3 * D_)          // 3072: [hi|lo|hi] x [hi|hi|lo] split concat
#define SCALE_ (1.0f / 64.0f)
#define NEG_ (-10000.0f)

// Scratch (static device globals — no runtime allocation allowed)
__device__ float g_q[M_ * D_];
__device__ float g_k[M_ * D_];
__device__ float g_v[M_ * D_];
__device__ float g_o[M_ * D_];
__device__ float2 g_cs[N_ * 32];                  // RoPE cos/sin table
__device__ __nv_bfloat16 g_x2[(size_t)M_ * K3_];  // x split [hi|lo|hi]
__device__ __nv_bfloat16 g_o2[(size_t)M_ * K3_];  // o split [hi|lo|hi]
__device__ __nv_bfloat16 g_wqkv[(size_t)(3 * D_) * K3_]; // Wq|Wk|Wv splits [hi|hi|lo]
__device__ __nv_bfloat16 g_wo2[(size_t)D_ * K3_];
// flash operands: hi/lo bf16, Q pre-scaled; V transposed per (b,h)
__device__ __nv_bfloat16 g_qh[(size_t)M_ * D_];
__device__ __nv_bfloat16 g_ql[(size_t)M_ * D_];
__device__ __nv_bfloat16 g_kh[(size_t)M_ * D_];
__device__ __nv_bfloat16 g_kl[(size_t)M_ * D_];
__device__ __nv_bfloat16 g_vth[(size_t)B_ * H_ * HD_ * N_];
__device__ __nv_bfloat16 g_vtl[(size_t)B_ * H_ * HD_ * N_];

__device__ __forceinline__ uint32_t smem_u32(const void* p) {
    uint32_t a;
    asm("{ .reg .u64 t; cvta.to.shared.u64 t, %1; cvt.u32.u64 %0, t; }"
        : "=r"(a) : "l"(p));
    return a;
}

#define CP16(dst, src) \
    asm volatile("cp.async.cg.shared.global [%0], [%1], 16;" :: "r"(dst), "l"(src))
#define LDMX4(r0, r1, r2, r3, addr) \
    asm volatile("ldmatrix.sync.aligned.m8n8.x4.shared.b16 {%0,%1,%2,%3}, [%4];" \
                 : "=r"(r0), "=r"(r1), "=r"(r2), "=r"(r3) : "r"(addr))
#define MMA4(dd, aa, b0, b1) \
    asm volatile("mma.sync.aligned.m16n8k16.row.col.f32.bf16.bf16.f32 " \
                 "{%0,%1,%2,%3}, {%4,%5,%6,%7}, {%8,%9}, {%0,%1,%2,%3};" \
                 : "+f"((dd)[0]), "+f"((dd)[1]), "+f"((dd)[2]), "+f"((dd)[3]) \
                 : "r"((aa)[0]), "r"((aa)[1]), "r"((aa)[2]), "r"((aa)[3]), \
                   "r"(b0), "r"(b1))

__device__ __forceinline__ void split_pack(float x, float y, uint32_t& hi, uint32_t& lo) {
    __nv_bfloat16 hx = __float2bfloat16(x), hy = __float2bfloat16(y);
    __nv_bfloat16 lx = __float2bfloat16(x - __bfloat162float(hx));
    __nv_bfloat16 ly = __float2bfloat16(y - __bfloat162float(hy));
    __nv_bfloat162 Hh{hx, hy}, Ll{lx, ly};
    hi = *(uint32_t*)&Hh;
    lo = *(uint32_t*)&Ll;
}

// ===========================================================================
// hi/lo bf16 split with 3-way concat (for projection GEMMs).
// ===========================================================================
__global__ void split_kernel(const float* __restrict__ src,
                             __nv_bfloat16* __restrict__ dst, int rows, int wmode)
{
    int gid = blockIdx.x * blockDim.x + threadIdx.x;
    int total = rows * (D_ / 4);
    if (gid >= total) return;
    int r = gid >> 8;
    int c4 = gid & 255;
    float4 xv = ((const float4*)src)[gid];
    float xs[4] = {xv.x, xv.y, xv.z, xv.w};
    __nv_bfloat162 hi2[2], lo2[2];
#pragma unroll
    for (int j = 0; j < 2; j++) {
        __nv_bfloat16 h0 = __float2bfloat16(xs[2 * j]);
        __nv_bfloat16 h1 = __float2bfloat16(xs[2 * j + 1]);
        __nv_bfloat16 l0 = __float2bfloat16(xs[2 * j] - __bfloat162float(h0));
        __nv_bfloat16 l1 = __float2bfloat16(xs[2 * j + 1] - __bfloat162float(h1));
        hi2[j] = __nv_bfloat162{h0, h1};
        lo2[j] = __nv_bfloat162{l0, l1};
    }
    __nv_bfloat162* d0 = (__nv_bfloat162*)(dst + (size_t)r * K3_) + c4 * 2;
    __nv_bfloat162* d1 = (__nv_bfloat162*)(dst + (size_t)r * K3_ + D_) + c4 * 2;
    __nv_bfloat162* d2 = (__nv_bfloat162*)(dst + (size_t)r * K3_ + 2 * D_) + c4 * 2;
    d0[0] = hi2[0]; d0[1] = hi2[1];
    if (wmode) { d1[0] = hi2[0]; d1[1] = hi2[1]; d2[0] = lo2[0]; d2[1] = lo2[1]; }
    else       { d1[0] = lo2[0]; d1[1] = lo2[1]; d2[0] = hi2[0]; d2[1] = hi2[1]; }
}

// ===========================================================================
// mma.sync bf16 GEMM, BK=64, 3-stage cp.async pipeline (one sync / 128 MMAs).
// C[bn] routed: bn<1024 -> C0, <2048 -> C1, else C2 (col = bn & 1023).
// ===========================================================================
#define BK 64
#define PITCH 72                          // bf16 elems/row (144 B; quad stride 9)
#define TILE_ELEMS (128 * PITCH)          // one operand per stage
#define STAGE_ELEMS (2 * TILE_ELEMS)
#define ST 3
#define MM_SMEM (ST * STAGE_ELEMS * 2)    // 110592 B

__global__ __launch_bounds__(256, 2) void mm_mma(
    const __nv_bfloat16* __restrict__ A, const __nv_bfloat16* __restrict__ Bw,
    const float* __restrict__ bias,
    float* __restrict__ C0, float* __restrict__ C1, float* __restrict__ C2)
{
    extern __shared__ __nv_bfloat16 dsm[];

    const int tid  = threadIdx.x;
    const int lane = tid & 31;
    const int wid  = tid >> 5;
    const int wm   = wid >> 2;
    const int wn   = wid & 3;
    const int bm   = blockIdx.y * 128;
    const int bn   = blockIdx.x * 128;

    const uint32_t base = smem_u32(dsm);

    // ldmatrix lane addressing (shared by A and B x4 loads)
    const uint32_t fRow = (uint32_t)(lane & 15);
    const uint32_t fKof = (uint32_t)((lane >> 4) << 3);

    float d[4][4][4];
#pragma unroll
    for (int mi = 0; mi < 4; mi++)
#pragma unroll
        for (int ni = 0; ni < 4; ni++)
#pragma unroll
            for (int r = 0; r < 4; r++) d[mi][ni][r] = 0.0f;

    const int NC = K3_ / BK;    // 48 chunks

    auto load_chunk = [&](int c, int stage) {
        uint32_t sA = base + (uint32_t)(stage * STAGE_ELEMS) * 2;
        uint32_t sB = sA + (uint32_t)TILE_ELEMS * 2;
#pragma unroll
        for (int t = 0; t < 4; t++) {
            int s = tid + t * 256;            // 0..1023
            int row = s >> 3, c16 = s & 7;
            uint32_t off = (uint32_t)(row * (PITCH * 2) + c16 * 16);
            const __nv_bfloat16* gA = A  + (size_t)(bm + row) * K3_ + c * BK + c16 * 8;
            const __nv_bfloat16* gB = Bw + (size_t)(bn + row) * K3_ + c * BK + c16 * 8;
            CP16(sA + off, gA);
            CP16(sB + off, gB);
        }
        asm volatile("cp.async.commit_group;");
    };

    load_chunk(0, 0);
    load_chunk(1, 1);

    for (int c = 0; c < NC; c++) {
        asm volatile("cp.async.wait_group 1;");
        __syncthreads();
        if (c + 2 < NC) load_chunk(c + 2, (c + 2) % ST);

        const int stage = c % ST;
        uint32_t sA = base + (uint32_t)(stage * STAGE_ELEMS) * 2;
        uint32_t sB = sA + (uint32_t)TILE_ELEMS * 2;

#pragma unroll
        for (int ks = 0; ks < 4; ks++) {
            uint32_t a[4][4], b[4][2];
#pragma unroll
            for (int mi = 0; mi < 4; mi++) {
                uint32_t addr = sA +
                    ((uint32_t)(wm * 64 + mi * 16) + fRow) * (PITCH * 2) +
                    ((uint32_t)(ks * 16) + fKof) * 2;
                LDMX4(a[mi][0], a[mi][1], a[mi][2], a[mi][3], addr);
            }
#pragma unroll
            for (int nj = 0; nj < 2; nj++) {       // n16 per x4 -> two n8 frags
                uint32_t r0, r1, r2, r3;
                uint32_t addr = sB +
                    ((uint32_t)(wn * 32 + nj * 16) + fRow) * (PITCH * 2) +
                    ((uint32_t)(ks * 16) + fKof) * 2;
                LDMX4(r0, r1, r2, r3, addr);
                b[2 * nj][0] = r0;     b[2 * nj][1] = r2;
                b[2 * nj + 1][0] = r1; b[2 * nj + 1][1] = r3;
            }
#pragma unroll
            for (int mi = 0; mi < 4; mi++)
#pragma unroll
                for (int ni = 0; ni < 4; ni++)
                    MMA4(d[mi][ni], a[mi], b[ni][0], b[ni][1]);
        }
    }

    // epilogue: route output by bn
    float* Cs = (bn < 1024) ? C0 : (bn < 2048) ? C1 : C2;
    const int cbase = bn & 1023;
#pragma unroll
    for (int mi = 0; mi < 4; mi++) {
        int r0 = bm + wm * 64 + mi * 16 + (lane >> 2);
#pragma unroll
        for (int ni = 0; ni < 4; ni++) {
            int cc = cbase + wn * 32 + ni * 8 + ((lane & 3) << 1);
            float b0 = bias ? bias[cc] : 0.0f;
            float b1 = bias ? bias[cc + 1] : 0.0f;
            *(float2*)&Cs[(size_t)r0 * D_ + cc] =
                make_float2(d[mi][ni][0] + b0, d[mi][ni][1] + b1);
            *(float2*)&Cs[(size_t)(r0 + 8) * D_ + cc] =
                make_float2(d[mi][ni][2] + b0, d[mi][ni][3] + b1);
        }
    }
}

// ===========================================================================
// RoPE cos/sin table build
// ===========================================================================
__global__ void build_cs_kernel()
{
    int gid = blockIdx.x * blockDim.x + threadIdx.x;
    if (gid >= N_ * 32) return;
    int pos = gid >> 5;
    int i   = gid & 31;
    float inv_f = (float)pow(10000.0, -(double)(2 * i) / 64.0);
    float ang   = (float)pos * inv_f;
    g_cs[gid] = make_float2((float)cos((double)ang), (float)sin((double)ang));
}

// ===========================================================================
// Fused RoPE + hi/lo split for Q (pre-scaled) and K.
// ===========================================================================
__global__ void rope_split_kernel(
    const float* __restrict__ q, const float* __restrict__ k,
    __nv_bfloat16* __restrict__ qh, __nv_bfloat16* __restrict__ ql,
    __nv_bfloat16* __restrict__ kh, __nv_bfloat16* __restrict__ kl)
{
    int gid = blockIdx.x * blockDim.x + threadIdx.x;
    if (gid >= M_ * 512) return;
    int row = gid >> 9;
    int p   = gid & 511;
    int i   = p & 31;
    int pos = row & (N_ - 1);
    float2 cs = g_cs[pos * 32 + i];

    float2 xq = ((const float2*)(q + (size_t)row * D_))[p];
    float qa = fmaf(xq.x, cs.x, -xq.y * cs.y) * SCALE_;
    float qb = fmaf(xq.y, cs.x,  xq.x * cs.y) * SCALE_;
    uint32_t qhi, qlo;
    split_pack(qa, qb, qhi, qlo);
    ((uint32_t*)(qh + (size_t)row * D_))[p] = qhi;
    ((uint32_t*)(ql + (size_t)row * D_))[p] = qlo;

    float2 xk = ((const float2*)(k + (size_t)row * D_))[p];
    float ka = fmaf(xk.x, cs.x, -xk.y * cs.y);
    float kb = fmaf(xk.y, cs.x,  xk.x * cs.y);
    uint32_t khi, klo;
    split_pack(ka, kb, khi, klo);
    ((uint32_t*)(kh + (size_t)row * D_))[p] = khi;
    ((uint32_t*)(kl + (size_t)row * D_))[p] = klo;
}

// ===========================================================================
// V split + transpose: v [b,n,h*64+d] f32 -> vth/vtl [b,h,d,n] bf16
// ===========================================================================
__global__ void v_split_t_kernel(const float* __restrict__ v,
                                 __nv_bfloat16* __restrict__ vth,
                                 __nv_bfloat16* __restrict__ vtl)
{
    __shared__ float tile[64][65];
    int n0 = blockIdx.x * 64, hh = blockIdx.y, b = blockIdx.z;
    int tid = threadIdx.x;
#pragma unroll
    for (int i = 0; i < 16; i++) {
        int idx = tid + i * 256;
        int r = idx >> 6, c = idx & 63;
        tile[r][c] = v[((size_t)(b * N_ + n0 + r)) * D_ + hh * HD_ + c];
    }
    __syncthreads();
#pragma unroll
    for (int i = 0; i < 16; i++) {
        int idx = tid + i * 256;
        int dd = idx >> 6, c = idx & 63;
        float val = tile[c][dd];
        __nv_bfloat16 hv = __float2bfloat16(val);
        __nv_bfloat16 lv = __float2bfloat16(val - __bfloat162float(hv));
        size_t off = ((size_t)((b * H_ + hh) * HD_ + dd)) * N_ + n0 + c;
        vth[off] = hv;
        vtl[off] = lv;
    }
}

// ===========================================================================
// Tensor-core causal flash attention with hi/lo split (unchanged).
// ===========================================================================
#define FP 72
#define FL_SMEM ((256 * FP + 2 * 2 * 64 * FP + 2 * 2 * 64 * FP) * 2)

__global__ __launch_bounds__(256, 1) void flash_mma(
    const __nv_bfloat16* __restrict__ qh, const __nv_bfloat16* __restrict__ ql,
    const __nv_bfloat16* __restrict__ kh, const __nv_bfloat16* __restrict__ kl,
    const __nv_bfloat16* __restrict__ vth, const __nv_bfloat16* __restrict__ vtl,
    float* __restrict__ o)
{
    extern __shared__ __nv_bfloat16 sm[];
    __nv_bfloat16* sQh = sm;
    __nv_bfloat16* sQl = sm + 128 * FP;
    __nv_bfloat16* sK  = sm + 256 * FP;
    __nv_bfloat16* sV  = sm + 256 * FP + 4 * 64 * FP;

    const int tid = threadIdx.x, lane = tid & 31, wid = tid >> 5;
    const int qb = blockIdx.x, h = blockIdx.y, b = blockIdx.z;
    const int qrow0 = qb * 128;

    {
#pragma unroll
        for (int i = 0; i < 8; i++) {
            int t = tid + i * 256;
            int tensor = t >> 10;
            int rem = t & 1023;
            int r = rem >> 3, s = rem & 7;
            uint32_t dst = smem_u32((tensor ? sQl : sQh) + r * FP) + s * 16;
            const __nv_bfloat16* src = (tensor ? ql : qh) +
                ((size_t)(b * N_ + qrow0 + r)) * D_ + h * HD_ + s * 8;
            CP16(dst, src);
        }
        asm volatile("cp.async.commit_group;");
    }

    auto load_kv = [&](int kb, int buf) {
#pragma unroll
        for (int i = 0; i < 8; i++) {
            int t = tid + i * 256;
            int tensor = t >> 9;
            int rem = t & 511;
            int r = rem >> 3, s = rem & 7;
            uint32_t dst;
            const __nv_bfloat16* src;
            if (tensor < 2) {
                dst = smem_u32(sK + ((buf * 2 + tensor) * 64 + r) * FP) + s * 16;
                src = (tensor ? kl : kh) +
                    ((size_t)(b * N_ + kb * 64 + r)) * D_ + h * HD_ + s * 8;
            } else {
                dst = smem_u32(sV + ((buf * 2 + (tensor - 2)) * 64 + r) * FP) + s * 16;
                src = ((tensor == 3) ? vtl : vth) +
                    ((size_t)((b * H_ + h) * HD_ + r)) * N_ + kb * 64 + s * 8;
            }
            CP16(dst, src);
        }
        asm volatile("cp.async.commit_group;");
    };

    load_kv(0, 0);
    asm volatile("cp.async.wait_group 0;");
    __syncthreads();

    uint32_t fqh[4][4], fql[4][4];
    {
        uint32_t rowa = (uint32_t)(wid * 16 + (lane & 15));
        uint32_t cola = (uint32_t)(((lane >> 4) & 1) * 8);
        uint32_t bqh = smem_u32(sQh), bql = smem_u32(sQl);
#pragma unroll
        for (int ks = 0; ks < 4; ks++) {
            uint32_t off = (rowa * FP + ks * 16 + cola) * 2;
            LDMX4(fqh[ks][0], fqh[ks][1], fqh[ks][2], fqh[ks][3], bqh + off);
            LDMX4(fql[ks][0], fql[ks][1], fql[ks][2], fql[ks][3], bql + off);
        }
    }

    float m0 = -1e30f, m1 = -1e30f, l0 = 0.0f, l1 = 0.0f;
    float oacc[8][4];
#pragma unroll
    for (int f = 0; f < 8; f++)
#pragma unroll
        for (int r = 0; r < 4; r++) oacc[f][r] = 0.0f;

    const uint32_t rowb = (uint32_t)((lane & 7) + ((lane >> 4) & 1) * 8);
    const uint32_t colb8 = (uint32_t)(((lane >> 3) & 1) * 8);
    const int kbmax = 2 * qb + 1;

    for (int kb = 0; kb <= kbmax; kb++) {
        const int buf = kb & 1;
        if (kb) {
            asm volatile("cp.async.wait_group 0;");
            __syncthreads();
        }
        if (kb < kbmax) load_kv(kb + 1, buf ^ 1);

        float sacc[8][4];
#pragma unroll
        for (int f = 0; f < 8; f++)
#pragma unroll
            for (int r = 0; r < 4; r++) sacc[f][r] = 0.0f;

        uint32_t kbh = smem_u32(sK + (buf * 2 + 0) * 64 * FP);
        uint32_t kbl = smem_u32(sK + (buf * 2 + 1) * 64 * FP);
#pragma unroll
        for (int ks = 0; ks < 4; ks++) {
#pragma unroll
            for (int g = 0; g < 4; g++) {
                uint32_t b0, b1, b2, b3;
                uint32_t off = ((16 * g + rowb) * FP + ks * 16 + colb8) * 2;
                LDMX4(b0, b1, b2, b3, kbh + off);
                MMA4(sacc[2 * g],     fqh[ks], b0, b1);
                MMA4(sacc[2 * g + 1], fqh[ks], b2, b3);
                MMA4(sacc[2 * g],     fql[ks], b0, b1);
                MMA4(sacc[2 * g + 1], fql[ks], b2, b3);
            }
        }
#pragma unroll
        for (int ks = 0; ks < 4; ks++) {
#pragma unroll
            for (int g = 0; g < 4; g++) {
                uint32_t b0, b1, b2, b3;
                uint32_t off = ((16 * g + rowb) * FP + ks * 16 + colb8) * 2;
                LDMX4(b0, b1, b2, b3, kbl + off);
                MMA4(sacc[2 * g],     fqh[ks], b0, b1);
                MMA4(sacc[2 * g + 1], fqh[ks], b2, b3);
            }
        }

        const int grow0 = qrow0 + wid * 16 + (lane >> 2);
        if (kb >= 2 * qb) {
#pragma unroll
            for (int f = 0; f < 8; f++) {
                int c = kb * 64 + f * 8 + 2 * (lane & 3);
                if (c     > grow0)     sacc[f][0] += NEG_;
                if (c + 1 > grow0)     sacc[f][1] += NEG_;
                if (c     > grow0 + 8) sacc[f][2] += NEG_;
                if (c + 1 > grow0 + 8) sacc[f][3] += NEG_;
            }
        }

        float mx0 = -1e30f, mx1 = -1e30f;
#pragma unroll
        for (int f = 0; f < 8; f++) {
            mx0 = fmaxf(mx0, fmaxf(sacc[f][0], sacc[f][1]));
            mx1 = fmaxf(mx1, fmaxf(sacc[f][2], sacc[f][3]));
        }
        mx0 = fmaxf(mx0, __shfl_xor_sync(0xffffffffu, mx0, 1));
        mx0 = fmaxf(mx0, __shfl_xor_sync(0xffffffffu, mx0, 2));
        mx1 = fmaxf(mx1, __shfl_xor_sync(0xffffffffu, mx1, 1));
        mx1 = fmaxf(mx1, __shfl_xor_sync(0xffffffffu, mx1, 2));
        float mn0 = fmaxf(m0, mx0), mn1 = fmaxf(m1, mx1);
        float a0 = __expf(m0 - mn0), a1 = __expf(m1 - mn1);
        m0 = mn0; m1 = mn1;
        float rs0 = 0.0f, rs1 = 0.0f;
#pragma unroll
        for (int f = 0; f < 8; f++) {
            sacc[f][0] = __expf(sacc[f][0] - mn0);
            sacc[f][1] = __expf(sacc[f][1] - mn0);
            sacc[f][2] = __expf(sacc[f][2] - mn1);
            sacc[f][3] = __expf(sacc[f][3] - mn1);
            rs0 += sacc[f][0] + sacc[f][1];
            rs1 += sacc[f][2] + sacc[f][3];
        }
        rs0 += __shfl_xor_sync(0xffffffffu, rs0, 1);
        rs0 += __shfl_xor_sync(0xffffffffu, rs0, 2);
        rs1 += __shfl_xor_sync(0xffffffffu, rs1, 1);
        rs1 += __shfl_xor_sync(0xffffffffu, rs1, 2);
        l0 = l0 * a0 + rs0;
        l1 = l1 * a1 + rs1;
#pragma unroll
        for (int f = 0; f < 8; f++) {
            oacc[f][0] *= a0; oacc[f][1] *= a0;
            oacc[f][2] *= a1; oacc[f][3] *= a1;
        }

        uint32_t ph[4][4], pl[4][4];
#pragma unroll
        for (int js = 0; js < 4; js++) {
            split_pack(sacc[2 * js][0],     sacc[2 * js][1],     ph[js][0], pl[js][0]);
            split_pack(sacc[2 * js][2],     sacc[2 * js][3],     ph[js][1], pl[js][1]);
            split_pack(sacc[2 * js + 1][0], sacc[2 * js + 1][1], ph[js][2], pl[js][2]);
            split_pack(sacc[2 * js + 1][2], sacc[2 * js + 1][3], ph[js][3], pl[js][3]);
        }

        uint32_t vbh = smem_u32(sV + (buf * 2 + 0) * 64 * FP);
        uint32_t vbl = smem_u32(sV + (buf * 2 + 1) * 64 * FP);
#pragma unroll
        for (int js = 0; js < 4; js++) {
#pragma unroll
            for (int g = 0; g < 4; g++) {
                uint32_t b0, b1, b2, b3;
                uint32_t off = ((16 * g + rowb) * FP + js * 16 + colb8) * 2;
                LDMX4(b0, b1, b2, b3, vbh + off);
                MMA4(oacc[2 * g],     ph[js], b0, b1);
                MMA4(oacc[2 * g + 1], ph[js], b2, b3);
                MMA4(oacc[2 * g],     pl[js], b0, b1);
                MMA4(oacc[2 * g + 1], pl[js], b2, b3);
            }
        }
#pragma unroll
        for (int js = 0; js < 4; js++) {
#pragma unroll
            for (int g = 0; g < 4; g++) {
                uint32_t b0, b1, b2, b3;
                uint32_t off = ((16 * g + rowb) * FP + js * 16 + colb8) * 2;
                LDMX4(b0, b1, b2, b3, vbl + off);
                MMA4(oacc[2 * g],     ph[js], b0, b1);
                MMA4(oacc[2 * g + 1], ph[js], b2, b3);
            }
        }
        __syncthreads();
    }

    const int grow0 = qrow0 + wid * 16 + (lane >> 2);
    float inv0 = 1.0f / l0, inv1 = 1.0f / l1;
    float* ob = o + ((size_t)(b * N_ + grow0)) * D_ + h * HD_;
#pragma unroll
    for (int f = 0; f < 8; f++) {
        int dcol = f * 8 + 2 * (lane & 3);
        *(float2*)(ob + dcol) =
            make_float2(oacc[f][0] * inv0, oacc[f][1] * inv0);
        *(float2*)(ob + 8 * D_ + dcol) =
            make_float2(oacc[f][2] * inv1, oacc[f][3] * inv1);
    }
}

// ---------------------------------------------------------------------------
extern "C" void kernel_launch(void* const* d_in, const int* in_sizes, int n_in,
                              void* d_out, int out_size)
{
    const float* x  = (const float*)d_in[0];
    const float* Wq = (const float*)d_in[1];
    const float* Wk = (const float*)d_in[2];
    const float* Wv = (const float*)d_in[3];
    const float* Wo = (const float*)d_in[4];
    const float* bo = (const float*)d_in[5];
    float* out = (float*)d_out;

    float *q, *k, *v, *o;
    __nv_bfloat16 *x2, *o2, *wqkv, *wo2;
    __nv_bfloat16 *qh, *ql, *kh, *kl, *vth, *vtl;
    cudaGetSymbolAddress((void**)&q, g_q);
    cudaGetSymbolAddress((void**)&k, g_k);
    cudaGetSymbolAddress((void**)&v, g_v);
    cudaGetSymbolAddress((void**)&o, g_o);
    cudaGetSymbolAddress((void**)&x2, g_x2);
    cudaGetSymbolAddress((void**)&o2, g_o2);
    cudaGetSymbolAddress((void**)&wqkv, g_wqkv);
    cudaGetSymbolAddress((void**)&wo2, g_wo2);
    cudaGetSymbolAddress((void**)&qh, g_qh);
    cudaGetSymbolAddress((void**)&ql, g_ql);
    cudaGetSymbolAddress((void**)&kh, g_kh);
    cudaGetSymbolAddress((void**)&kl, g_kl);
    cudaGetSymbolAddress((void**)&vth, g_vth);
    cudaGetSymbolAddress((void**)&vtl, g_vtl);

    cudaFuncSetAttribute(flash_mma, cudaFuncAttributeMaxDynamicSharedMemorySize,
                         (int)FL_SMEM);
    cudaFuncSetAttribute(mm_mma, cudaFuncAttributeMaxDynamicSharedMemorySize,
                         (int)MM_SMEM);

    // Launch order arranged so launch #6 (ncu -s 5 -c 1) is the QKV GEMM.
    build_cs_kernel<<<(N_ * 32 + 255) / 256, 256>>>();                     // 1

    int xthreads = M_ * (D_ / 4);
    int wthreads = D_ * (D_ / 4);
    split_kernel<<<(xthreads + 255) / 256, 256>>>(x, x2, M_, 0);           // 2
    split_kernel<<<(wthreads + 255) / 256, 256>>>(Wq, wqkv, D_, 1);        // 3
    split_kernel<<<(wthreads + 255) / 256, 256>>>(Wk, wqkv + (size_t)D_ * K3_, D_, 1);     // 4
    split_kernel<<<(wthreads + 255) / 256, 256>>>(Wv, wqkv + (size_t)2 * D_ * K3_, D_, 1); // 5

    dim3 qkvgrid(3 * D_ / 128, M_ / 128);  // (24, 64)
    mm_mma<<<qkvgrid, 256, MM_SMEM>>>(x2, wqkv, nullptr, q, k, v);         // 6 <- profiled

    int rpairs = M_ * 512;
    rope_split_kernel<<<(rpairs + 255) / 256, 256>>>(q, k, qh, ql, kh, kl); // 7
    dim3 vgrid(N_ / 64, H_, B_);
    v_split_t_kernel<<<vgrid, 256>>>(v, vth, vtl);                          // 8
    split_kernel<<<(wthreads + 255) / 256, 256>>>(Wo, wo2, D_, 1);          // 9

    dim3 fgrid(N_ / 128, H_, B_);     // (16, 16, 4)
    flash_mma<<<fgrid, 256, FL_SMEM>>>(qh, ql, kh, kl, vth, vtl, o);        // 10

    split_kernel<<<(xthreads + 255) / 256, 256>>>(o, o2, M_, 0);            // 11
    dim3 ogrid(D_ / 128, M_ / 128);   // (8, 64)
    mm_mma<<<ogrid, 256, MM_SMEM>>>(o2, wo2, bo, out, nullptr, nullptr);    // 12
}

// round 9
// speedup vs baseline: 6.0960x; 1.3863x over previous
#include <cuda_runtime.h>
#include <cuda_fp16.h>
#include <math.h>
#include <cstdint>

// Problem constants
#define B_ 4
#define N_ 2048
#define D_ 1024
#define H_ 16
#define HD_ 64
#define M_ (B_ * N_)          // 8192 rows
#define K2_ (2 * D_)          // 2048: act [ah|al]; weight read as [wh|wh]
#define SCALE_ (1.0f / 64.0f)
#define NEG_ (-10000.0f)

// Scratch (static device globals — no runtime allocation allowed)
__device__ float g_q[M_ * D_];
__device__ float g_k[M_ * D_];
__device__ float g_v[M_ * D_];
__device__ float g_o[M_ * D_];
__device__ float2 g_cs[N_ * 32];                 // RoPE cos/sin table
__device__ __half g_x2[(size_t)M_ * K2_];        // x  split [ah|al]
__device__ __half g_o2[(size_t)M_ * K2_];        // o  split [ah|al]
__device__ __half g_wqkv[(size_t)(3 * D_) * D_]; // Wq|Wk|Wv hi fp16 [3072 x 1024]
__device__ __half g_wo2[(size_t)D_ * D_];        // Wo hi fp16
// flash operands (fp16): Q 2-term, K/V hi only; V transposed per (b,h)
__device__ __half g_qh[(size_t)M_ * D_];
__device__ __half g_ql[(size_t)M_ * D_];
__device__ __half g_kh[(size_t)M_ * D_];
__device__ __half g_vth[(size_t)B_ * H_ * HD_ * N_];

__device__ __forceinline__ uint32_t smem_u32(const void* p) {
    uint32_t a;
    asm("{ .reg .u64 t; cvta.to.shared.u64 t, %1; cvt.u32.u64 %0, t; }"
        : "=r"(a) : "l"(p));
    return a;
}

#define CP16(dst, src) \
    asm volatile("cp.async.cg.shared.global [%0], [%1], 16;" :: "r"(dst), "l"(src))
#define LDMX4(r0, r1, r2, r3, addr) \
    asm volatile("ldmatrix.sync.aligned.m8n8.x4.shared.b16 {%0,%1,%2,%3}, [%4];" \
                 : "=r"(r0), "=r"(r1), "=r"(r2), "=r"(r3) : "r"(addr))
#define MMA4(dd, aa, b0, b1) \
    asm volatile("mma.sync.aligned.m16n8k16.row.col.f32.f16.f16.f32 " \
                 "{%0,%1,%2,%3}, {%4,%5,%6,%7}, {%8,%9}, {%0,%1,%2,%3};" \
                 : "+f"((dd)[0]), "+f"((dd)[1]), "+f"((dd)[2]), "+f"((dd)[3]) \
                 : "r"((aa)[0]), "r"((aa)[1]), "r"((aa)[2]), "r"((aa)[3]), \
                   "r"(b0), "r"(b1))

__device__ __forceinline__ void split_pack_h(float x, float y, uint32_t& hi, uint32_t& lo) {
    __half hx = __float2half(x), hy = __float2half(y);
    __half lx = __float2half(x - __half2float(hx));
    __half ly = __float2half(y - __half2float(hy));
    __half2 Hh{hx, hy}, Ll{lx, ly};
    hi = *(uint32_t*)&Hh;
    lo = *(uint32_t*)&Ll;
}

// ===========================================================================
// Activation split: src [rows x 1024] f32 -> dst [rows x 2048] fp16 [ah|al]
// ===========================================================================
__global__ void act_split_kernel(const float* __restrict__ src,
                                 __half* __restrict__ dst, int rows)
{
    int gid = blockIdx.x * blockDim.x + threadIdx.x;   // one float4
    int total = rows * (D_ / 4);
    if (gid >= total) return;
    int r = gid >> 8;
    int c4 = gid & 255;
    float4 xv = ((const float4*)src)[gid];
    uint32_t h0, l0, h1, l1;
    split_pack_h(xv.x, xv.y, h0, l0);
    split_pack_h(xv.z, xv.w, h1, l1);
    uint32_t* dh = (uint32_t*)(dst + (size_t)r * K2_) + c4 * 2;
    uint32_t* dl = (uint32_t*)(dst + (size_t)r * K2_ + D_) + c4 * 2;
    dh[0] = h0; dh[1] = h1;
    dl[0] = l0; dl[1] = l1;
}

// Weight hi-cast: src [rows x 1024] f32 -> dst [rows x 1024] fp16 (hi only)
__global__ void w_cast_kernel(const float* __restrict__ src,
                              __half* __restrict__ dst, int rows)
{
    int gid = blockIdx.x * blockDim.x + threadIdx.x;   // one float4
    int total = rows * (D_ / 4);
    if (gid >= total) return;
    float4 xv = ((const float4*)src)[gid];
    __half2 h0{__float2half(xv.x), __float2half(xv.y)};
    __half2 h1{__float2half(xv.z), __float2half(xv.w)};
    ((__half2*)dst)[gid * 2]     = h0;
    ((__half2*)dst)[gid * 2 + 1] = h1;
}

// ===========================================================================
// mma.sync fp16 GEMM: C = A2[rows x 2048] @ [Wh|Wh][ncols x 2048]^T (+bias)
// Weight stored [ncols x 1024]; loader reuses cols for chunks >= 16.
// BK=64, 3-stage cp.async pipeline. C routed by bn to C0/C1/C2.
// ===========================================================================
#define BK 64
#define PITCH 72
#define TILE_ELEMS (128 * PITCH)
#define STAGE_ELEMS (2 * TILE_ELEMS)
#define ST 3
#define MM_SMEM (ST * STAGE_ELEMS * 2)

__global__ __launch_bounds__(256, 2) void mm_mma(
    const __half* __restrict__ A, const __half* __restrict__ Bw,
    const float* __restrict__ bias,
    float* __restrict__ C0, float* __restrict__ C1, float* __restrict__ C2)
{
    extern __shared__ __half dsm[];

    const int tid  = threadIdx.x;
    const int lane = tid & 31;
    const int wid  = tid >> 5;
    const int wm   = wid >> 2;
    const int wn   = wid & 3;
    const int bm   = blockIdx.y * 128;
    const int bn   = blockIdx.x * 128;

    const uint32_t base = smem_u32(dsm);
    const uint32_t fRow = (uint32_t)(lane & 15);
    const uint32_t fKof = (uint32_t)((lane >> 4) << 3);

    float d[4][4][4];
#pragma unroll
    for (int mi = 0; mi < 4; mi++)
#pragma unroll
        for (int ni = 0; ni < 4; ni++)
#pragma unroll
            for (int r = 0; r < 4; r++) d[mi][ni][r] = 0.0f;

    const int NC = K2_ / BK;    // 32 chunks

    auto load_chunk = [&](int c, int stage) {
        uint32_t sA = base + (uint32_t)(stage * STAGE_ELEMS) * 2;
        uint32_t sB = sA + (uint32_t)TILE_ELEMS * 2;
        const int cw = (c & 15);           // weight chunk (cols reused)
#pragma unroll
        for (int t = 0; t < 4; t++) {
            int s = tid + t * 256;
            int row = s >> 3, c16 = s & 7;
            uint32_t off = (uint32_t)(row * (PITCH * 2) + c16 * 16);
            const __half* gA = A  + (size_t)(bm + row) * K2_ + c * BK + c16 * 8;
            const __half* gB = Bw + (size_t)(bn + row) * D_ + cw * BK + c16 * 8;
            CP16(sA + off, gA);
            CP16(sB + off, gB);
        }
        asm volatile("cp.async.commit_group;");
    };

    load_chunk(0, 0);
    load_chunk(1, 1);

    for (int c = 0; c < NC; c++) {
        asm volatile("cp.async.wait_group 1;");
        __syncthreads();
        if (c + 2 < NC) load_chunk(c + 2, (c + 2) % ST);

        const int stage = c % ST;
        uint32_t sA = base + (uint32_t)(stage * STAGE_ELEMS) * 2;
        uint32_t sB = sA + (uint32_t)TILE_ELEMS * 2;

#pragma unroll
        for (int ks = 0; ks < 4; ks++) {
            uint32_t a[4][4], b[4][2];
#pragma unroll
            for (int mi = 0; mi < 4; mi++) {
                uint32_t addr = sA +
                    ((uint32_t)(wm * 64 + mi * 16) + fRow) * (PITCH * 2) +
                    ((uint32_t)(ks * 16) + fKof) * 2;
                LDMX4(a[mi][0], a[mi][1], a[mi][2], a[mi][3], addr);
            }
#pragma unroll
            for (int nj = 0; nj < 2; nj++) {
                uint32_t r0, r1, r2, r3;
                uint32_t addr = sB +
                    ((uint32_t)(wn * 32 + nj * 16) + fRow) * (PITCH * 2) +
                    ((uint32_t)(ks * 16) + fKof) * 2;
                LDMX4(r0, r1, r2, r3, addr);
                b[2 * nj][0] = r0;     b[2 * nj][1] = r2;
                b[2 * nj + 1][0] = r1; b[2 * nj + 1][1] = r3;
            }
#pragma unroll
            for (int mi = 0; mi < 4; mi++)
#pragma unroll
                for (int ni = 0; ni < 4; ni++)
                    MMA4(d[mi][ni], a[mi], b[ni][0], b[ni][1]);
        }
    }

    float* Cs = (bn < 1024) ? C0 : (bn < 2048) ? C1 : C2;
    const int cbase = bn & 1023;
#pragma unroll
    for (int mi = 0; mi < 4; mi++) {
        int r0 = bm + wm * 64 + mi * 16 + (lane >> 2);
#pragma unroll
        for (int ni = 0; ni < 4; ni++) {
            int cc = cbase + wn * 32 + ni * 8 + ((lane & 3) << 1);
            float b0 = bias ? bias[cc] : 0.0f;
            float b1 = bias ? bias[cc + 1] : 0.0f;
            *(float2*)&Cs[(size_t)r0 * D_ + cc] =
                make_float2(d[mi][ni][0] + b0, d[mi][ni][1] + b1);
            *(float2*)&Cs[(size_t)(r0 + 8) * D_ + cc] =
                make_float2(d[mi][ni][2] + b0, d[mi][ni][3] + b1);
        }
    }
}

// ===========================================================================
// RoPE cos/sin table build
// ===========================================================================
__global__ void build_cs_kernel()
{
    int gid = blockIdx.x * blockDim.x + threadIdx.x;
    if (gid >= N_ * 32) return;
    int pos = gid >> 5;
    int i   = gid & 31;
    float inv_f = (float)pow(10000.0, -(double)(2 * i) / 64.0);
    float ang   = (float)pos * inv_f;
    g_cs[gid] = make_float2((float)cos((double)ang), (float)sin((double)ang));
}

// ===========================================================================
// Fused RoPE + fp16 split: Q -> qh+ql (unscaled), K -> kh (hi only)
// ===========================================================================
__global__ void rope_split_kernel(
    const float* __restrict__ q, const float* __restrict__ k,
    __half* __restrict__ qh, __half* __restrict__ ql,
    __half* __restrict__ kh)
{
    int gid = blockIdx.x * blockDim.x + threadIdx.x;
    if (gid >= M_ * 512) return;
    int row = gid >> 9;
    int p   = gid & 511;
    int i   = p & 31;
    int pos = row & (N_ - 1);
    float2 cs = g_cs[pos * 32 + i];

    float2 xq = ((const float2*)(q + (size_t)row * D_))[p];
    float qa = fmaf(xq.x, cs.x, -xq.y * cs.y);
    float qb = fmaf(xq.y, cs.x,  xq.x * cs.y);
    uint32_t qhi, qlo;
    split_pack_h(qa, qb, qhi, qlo);
    ((uint32_t*)(qh + (size_t)row * D_))[p] = qhi;
    ((uint32_t*)(ql + (size_t)row * D_))[p] = qlo;

    float2 xk = ((const float2*)(k + (size_t)row * D_))[p];
    float ka = fmaf(xk.x, cs.x, -xk.y * cs.y);
    float kb = fmaf(xk.y, cs.x,  xk.x * cs.y);
    __half2 kh2{__float2half(ka), __float2half(kb)};
    ((uint32_t*)(kh + (size_t)row * D_))[p] = *(uint32_t*)&kh2;
}

// ===========================================================================
// V cast + transpose: v [b,n,h*64+d] f32 -> vth [b,h,d,n] fp16
// ===========================================================================
__global__ void v_split_t_kernel(const float* __restrict__ v,
                                 __half* __restrict__ vth)
{
    __shared__ float tile[64][65];
    int n0 = blockIdx.x * 64, hh = blockIdx.y, b = blockIdx.z;
    int tid = threadIdx.x;
#pragma unroll
    for (int i = 0; i < 16; i++) {
        int idx = tid + i * 256;
        int r = idx >> 6, c = idx & 63;
        tile[r][c] = v[((size_t)(b * N_ + n0 + r)) * D_ + hh * HD_ + c];
    }
    __syncthreads();
#pragma unroll
    for (int i = 0; i < 16; i++) {
        int idx = tid + i * 256;
        int dd = idx >> 6, c = idx & 63;
        size_t off = ((size_t)((b * H_ + hh) * HD_ + dd)) * N_ + n0 + c;
        vth[off] = __float2half(tile[c][dd]);
    }
}

// ===========================================================================
// Tensor-core causal flash attention, fp16 2-term.
// S = (Qh+Ql).Kh (scaled post-MMA); O += (Ph+Pl).Vh
// smem 72KB -> 2 CTAs/SM. Heavy q-tiles scheduled first.
// ===========================================================================
#define FP 72
#define FL_SMEM ((256 * FP + 2 * 64 * FP + 2 * 64 * FP) * 2)

__global__ __launch_bounds__(256, 2) void flash_mma(
    const __half* __restrict__ qh, const __half* __restrict__ ql,
    const __half* __restrict__ kh, const __half* __restrict__ vth,
    float* __restrict__ o)
{
    extern __shared__ __half sm[];
    __half* sQh = sm;                       // [128][FP]
    __half* sQl = sm + 128 * FP;
    __half* sK  = sm + 256 * FP;            // [2 buf][64][FP]
    __half* sV  = sm + 256 * FP + 2 * 64 * FP;

    const int tid = threadIdx.x, lane = tid & 31, wid = tid >> 5;
    const int qb = (int)(gridDim.x - 1 - blockIdx.x);   // heavy tiles first
    const int h = blockIdx.y, b = blockIdx.z;
    const int qrow0 = qb * 128;

    {
#pragma unroll
        for (int i = 0; i < 8; i++) {
            int t = tid + i * 256;
            int tensor = t >> 10;
            int rem = t & 1023;
            int r = rem >> 3, s = rem & 7;
            uint32_t dst = smem_u32((tensor ? sQl : sQh) + r * FP) + s * 16;
            const __half* src = (tensor ? ql : qh) +
                ((size_t)(b * N_ + qrow0 + r)) * D_ + h * HD_ + s * 8;
            CP16(dst, src);
        }
        asm volatile("cp.async.commit_group;");
    }

    auto load_kv = [&](int kb, int buf) {
#pragma unroll
        for (int i = 0; i < 4; i++) {
            int t = tid + i * 256;             // 0..1023
            int tensor = t >> 9;               // 0 Kh, 1 Vh
            int rem = t & 511;
            int r = rem >> 3, s = rem & 7;
            uint32_t dst;
            const __half* src;
            if (tensor == 0) {
                dst = smem_u32(sK + (buf * 64 + r) * FP) + s * 16;
                src = kh + ((size_t)(b * N_ + kb * 64 + r)) * D_ + h * HD_ + s * 8;
            } else {
                dst = smem_u32(sV + (buf * 64 + r) * FP) + s * 16;
                src = vth + ((size_t)((b * H_ + h) * HD_ + r)) * N_ + kb * 64 + s * 8;
            }
            CP16(dst, src);
        }
        asm volatile("cp.async.commit_group;");
    };

    load_kv(0, 0);
    asm volatile("cp.async.wait_group 0;");
    __syncthreads();

    uint32_t fqh[4][4], fql[4][4];
    {
        uint32_t rowa = (uint32_t)(wid * 16 + (lane & 15));
        uint32_t cola = (uint32_t)(((lane >> 4) & 1) * 8);
        uint32_t bqh = smem_u32(sQh), bql = smem_u32(sQl);
#pragma unroll
        for (int ks = 0; ks < 4; ks++) {
            uint32_t off = (rowa * FP + ks * 16 + cola) * 2;
            LDMX4(fqh[ks][0], fqh[ks][1], fqh[ks][2], fqh[ks][3], bqh + off);
            LDMX4(fql[ks][0], fql[ks][1], fql[ks][2], fql[ks][3], bql + off);
        }
    }

    float m0 = -1e30f, m1 = -1e30f, l0 = 0.0f, l1 = 0.0f;
    float oacc[8][4];
#pragma unroll
    for (int f = 0; f < 8; f++)
#pragma unroll
        for (int r = 0; r < 4; r++) oacc[f][r] = 0.0f;

    const uint32_t rowb = (uint32_t)((lane & 7) + ((lane >> 4) & 1) * 8);
    const uint32_t colb8 = (uint32_t)(((lane >> 3) & 1) * 8);
    const int kbmax = 2 * qb + 1;

    for (int kb = 0; kb <= kbmax; kb++) {
        const int buf = kb & 1;
        if (kb) {
            asm volatile("cp.async.wait_group 0;");
            __syncthreads();
        }
        if (kb < kbmax) load_kv(kb + 1, buf ^ 1);

        float sacc[8][4];
#pragma unroll
        for (int f = 0; f < 8; f++)
#pragma unroll
            for (int r = 0; r < 4; r++) sacc[f][r] = 0.0f;

        uint32_t kbh = smem_u32(sK + buf * 64 * FP);
#pragma unroll
        for (int ks = 0; ks < 4; ks++) {
#pragma unroll
            for (int g = 0; g < 4; g++) {
                uint32_t b0, b1, b2, b3;
                uint32_t off = ((16 * g + rowb) * FP + ks * 16 + colb8) * 2;
                LDMX4(b0, b1, b2, b3, kbh + off);
                MMA4(sacc[2 * g],     fqh[ks], b0, b1);
                MMA4(sacc[2 * g + 1], fqh[ks], b2, b3);
                MMA4(sacc[2 * g],     fql[ks], b0, b1);
                MMA4(sacc[2 * g + 1], fql[ks], b2, b3);
            }
        }

        // scale post-MMA (Q kept unscaled to keep Ql out of fp16 subnormals)
#pragma unroll
        for (int f = 0; f < 8; f++)
#pragma unroll
            for (int r = 0; r < 4; r++) sacc[f][r] *= SCALE_;

        const int grow0 = qrow0 + wid * 16 + (lane >> 2);
        if (kb >= 2 * qb) {
#pragma unroll
            for (int f = 0; f < 8; f++) {
                int c = kb * 64 + f * 8 + 2 * (lane & 3);
                if (c     > grow0)     sacc[f][0] += NEG_;
                if (c + 1 > grow0)     sacc[f][1] += NEG_;
                if (c     > grow0 + 8) sacc[f][2] += NEG_;
                if (c + 1 > grow0 + 8) sacc[f][3] += NEG_;
            }
        }

        float mx0 = -1e30f, mx1 = -1e30f;
#pragma unroll
        for (int f = 0; f < 8; f++) {
            mx0 = fmaxf(mx0, fmaxf(sacc[f][0], sacc[f][1]));
            mx1 = fmaxf(mx1, fmaxf(sacc[f][2], sacc[f][3]));
        }
        mx0 = fmaxf(mx0, __shfl_xor_sync(0xffffffffu, mx0, 1));
        mx0 = fmaxf(mx0, __shfl_xor_sync(0xffffffffu, mx0, 2));
        mx1 = fmaxf(mx1, __shfl_xor_sync(0xffffffffu, mx1, 1));
        mx1 = fmaxf(mx1, __shfl_xor_sync(0xffffffffu, mx1, 2));
        float mn0 = fmaxf(m0, mx0), mn1 = fmaxf(m1, mx1);
        float a0 = __expf(m0 - mn0), a1 = __expf(m1 - mn1);
        m0 = mn0; m1 = mn1;
        float rs0 = 0.0f, rs1 = 0.0f;
#pragma unroll
        for (int f = 0; f < 8; f++) {
            sacc[f][0] = __expf(sacc[f][0] - mn0);
            sacc[f][1] = __expf(sacc[f][1] - mn0);
            sacc[f][2] = __expf(sacc[f][2] - mn1);
            sacc[f][3] = __expf(sacc[f][3] - mn1);
            rs0 += sacc[f][0] + sacc[f][1];
            rs1 += sacc[f][2] + sacc[f][3];
        }
        rs0 += __shfl_xor_sync(0xffffffffu, rs0, 1);
        rs0 += __shfl_xor_sync(0xffffffffu, rs0, 2);
        rs1 += __shfl_xor_sync(0xffffffffu, rs1, 1);
        rs1 += __shfl_xor_sync(0xffffffffu, rs1, 2);
        l0 = l0 * a0 + rs0;
        l1 = l1 * a1 + rs1;
#pragma unroll
        for (int f = 0; f < 8; f++) {
            oacc[f][0] *= a0; oacc[f][1] *= a0;
            oacc[f][2] *= a1; oacc[f][3] *= a1;
        }

        uint32_t ph[4][4], pl[4][4];
#pragma unroll
        for (int js = 0; js < 4; js++) {
            split_pack_h(sacc[2 * js][0],     sacc[2 * js][1],     ph[js][0], pl[js][0]);
            split_pack_h(sacc[2 * js][2],     sacc[2 * js][3],     ph[js][1], pl[js][1]);
            split_pack_h(sacc[2 * js + 1][0], sacc[2 * js + 1][1], ph[js][2], pl[js][2]);
            split_pack_h(sacc[2 * js + 1][2], sacc[2 * js + 1][3], ph[js][3], pl[js][3]);
        }

        uint32_t vbh = smem_u32(sV + buf * 64 * FP);
#pragma unroll
        for (int js = 0; js < 4; js++) {
#pragma unroll
            for (int g = 0; g < 4; g++) {
                uint32_t b0, b1, b2, b3;
                uint32_t off = ((16 * g + rowb) * FP + js * 16 + colb8) * 2;
                LDMX4(b0, b1, b2, b3, vbh + off);
                MMA4(oacc[2 * g],     ph[js], b0, b1);
                MMA4(oacc[2 * g + 1], ph[js], b2, b3);
                MMA4(oacc[2 * g],     pl[js], b0, b1);
                MMA4(oacc[2 * g + 1], pl[js], b2, b3);
            }
        }
        __syncthreads();
    }

    const int grow0 = qrow0 + wid * 16 + (lane >> 2);
    float inv0 = 1.0f / l0, inv1 = 1.0f / l1;
    float* ob = o + ((size_t)(b * N_ + grow0)) * D_ + h * HD_;
#pragma unroll
    for (int f = 0; f < 8; f++) {
        int dcol = f * 8 + 2 * (lane & 3);
        *(float2*)(ob + dcol) =
            make_float2(oacc[f][0] * inv0, oacc[f][1] * inv0);
        *(float2*)(ob + 8 * D_ + dcol) =
            make_float2(oacc[f][2] * inv1, oacc[f][3] * inv1);
    }
}

// ---------------------------------------------------------------------------
extern "C" void kernel_launch(void* const* d_in, const int* in_sizes, int n_in,
                              void* d_out, int out_size)
{
    const float* x  = (const float*)d_in[0];
    const float* Wq = (const float*)d_in[1];
    const float* Wk = (const float*)d_in[2];
    const float* Wv = (const float*)d_in[3];
    const float* Wo = (const float*)d_in[4];
    const float* bo = (const float*)d_in[5];
    float* out = (float*)d_out;

    float *q, *k, *v, *o;
    __half *x2, *o2, *wqkv, *wo2, *qh, *ql, *kh, *vth;
    cudaGetSymbolAddress((void**)&q, g_q);
    cudaGetSymbolAddress((void**)&k, g_k);
    cudaGetSymbolAddress((void**)&v, g_v);
    cudaGetSymbolAddress((void**)&o, g_o);
    cudaGetSymbolAddress((void**)&x2, g_x2);
    cudaGetSymbolAddress((void**)&o2, g_o2);
    cudaGetSymbolAddress((void**)&wqkv, g_wqkv);
    cudaGetSymbolAddress((void**)&wo2, g_wo2);
    cudaGetSymbolAddress((void**)&qh, g_qh);
    cudaGetSymbolAddress((void**)&ql, g_ql);
    cudaGetSymbolAddress((void**)&kh, g_kh);
    cudaGetSymbolAddress((void**)&vth, g_vth);

    cudaFuncSetAttribute(flash_mma, cudaFuncAttributeMaxDynamicSharedMemorySize,
                         (int)FL_SMEM);
    cudaFuncSetAttribute(mm_mma, cudaFuncAttributeMaxDynamicSharedMemorySize,
                         (int)MM_SMEM);

    build_cs_kernel<<<(N_ * 32 + 255) / 256, 256>>>();

    int xthreads = M_ * (D_ / 4);
    int wthreads = D_ * (D_ / 4);
    act_split_kernel<<<(xthreads + 255) / 256, 256>>>(x, x2, M_);
    w_cast_kernel<<<(wthreads + 255) / 256, 256>>>(Wq, wqkv, D_);
    w_cast_kernel<<<(wthreads + 255) / 256, 256>>>(Wk, wqkv + (size_t)D_ * D_, D_);
    w_cast_kernel<<<(wthreads + 255) / 256, 256>>>(Wv, wqkv + (size_t)2 * D_ * D_, D_);

    // fused QKV projection
    dim3 qkvgrid(3 * D_ / 128, M_ / 128);  // (24, 64)
    mm_mma<<<qkvgrid, 256, MM_SMEM>>>(x2, wqkv, nullptr, q, k, v);

    int rpairs = M_ * 512;
    rope_split_kernel<<<(rpairs + 255) / 256, 256>>>(q, k, qh, ql, kh);
    dim3 vgrid(N_ / 64, H_, B_);
    v_split_t_kernel<<<vgrid, 256>>>(v, vth);
    w_cast_kernel<<<(wthreads + 255) / 256, 256>>>(Wo, wo2, D_);

    dim3 fgrid(N_ / 128, H_, B_);     // (16, 16, 4)
    flash_mma<<<fgrid, 256, FL_SMEM>>>(qh, ql, kh, vth, o);

    act_split_kernel<<<(xthreads + 255) / 256, 256>>>(o, o2, M_);
    dim3 ogrid(D_ / 128, M_ / 128);   // (8, 64)
    mm_mma<<<ogrid, 256, MM_SMEM>>>(o2, wo2, bo, out, nullptr, nullptr);
}